// round 13
// baseline (speedup 1.0000x reference)
#include <cuda_runtime.h>
#include <cuda_fp16.h>
#include <math.h>
#include <stdint.h>

// ===========================================================================
// AttentionBlock B=8,S=2048,D=512 — mma.sync fp16, precision-tiered GEMMs
// R13: k-path eliminated via M = scale*(Wq Wk^T) (softmax-invariant terms
//      dropped, column correction c_t in softmax); merged weight transposes;
//      vectorized rowln/softmax.
// ===========================================================================

#define MTOT (16384 * 512)
__device__ __half g_xh[MTOT];
__device__ __half g_yh[MTOT];                       // y = x @ M
__device__ __half g_vth[MTOT];                      // v^T [512][16384]
__device__ __half g_ath[MTOT];                      // att fp16
__device__ __half g_onh[MTOT], g_onl[MTOT];
__device__ __half g_th[MTOT],  g_tl[MTOT];
__device__ __half g_hh[MTOT],  g_hl[MTOT];
__device__ __half g_h2h[MTOT], g_h2l[MTOT];
__device__ __half g_sh[8LL * 2048 * 2048];
__device__ __half g_wth[6 * 512 * 512];             // slot0=Mt, 2..5 = Wv,W1,W2,W3 ^T
__device__ __half g_wqh[512 * 512], g_wkh[512 * 512];
__device__ float g_u[512];
__device__ float g_c[16384];

// ---------------- helpers ----------------
__device__ __forceinline__ uint32_t smem_u32(const void* p) {
    uint32_t a;
    asm("{ .reg .u64 t; cvta.to.shared.u64 t, %1; cvt.u32.u64 %0, t; }"
        : "=r"(a) : "l"(p));
    return a;
}
__device__ __forceinline__ void cpa16(uint32_t dst, const void* src) {
    asm volatile("cp.async.cg.shared.global [%0], [%1], 16;"
                 :: "r"(dst), "l"(src) : "memory");
}
#define CP_COMMIT() asm volatile("cp.async.commit_group;" ::: "memory")
#define CP_WAIT0()  asm volatile("cp.async.wait_group 0;"  ::: "memory")
#define CP_WAIT1()  asm volatile("cp.async.wait_group 1;"  ::: "memory")
#define CP_WAIT2()  asm volatile("cp.async.wait_group 2;"  ::: "memory")

#define MMA_F16(c, a0, a1, a2, a3, b0, b1)                                    \
    asm volatile("mma.sync.aligned.m16n8k16.row.col.f32.f16.f16.f32 "         \
        "{%0,%1,%2,%3}, {%4,%5,%6,%7}, {%8,%9}, {%0,%1,%2,%3};"               \
        : "+f"((c)[0]), "+f"((c)[1]), "+f"((c)[2]), "+f"((c)[3])              \
        : "r"(a0), "r"(a1), "r"(a2), "r"(a3), "r"(b0), "r"(b1))

#define MMA_H16(c, a0, a1, a2, a3, b0, b1)                                    \
    asm volatile("mma.sync.aligned.m16n8k16.row.col.f16.f16.f16.f16 "         \
        "{%0,%1}, {%2,%3,%4,%5}, {%6,%7}, {%0,%1};"                           \
        : "+r"((c)[0]), "+r"((c)[1])                                          \
        : "r"(a0), "r"(a1), "r"(a2), "r"(a3), "r"(b0), "r"(b1))

__device__ __forceinline__ void ldsm_x4(uint32_t& r0, uint32_t& r1,
                                        uint32_t& r2, uint32_t& r3, uint32_t a) {
    asm volatile("ldmatrix.sync.aligned.m8n8.x4.shared.b16 {%0,%1,%2,%3}, [%4];"
                 : "=r"(r0), "=r"(r1), "=r"(r2), "=r"(r3) : "r"(a));
}

__device__ __forceinline__ void split2(float a, float b, __half2& h, __half2& l) {
    h = __floats2half2_rn(a, b);
    l = __floats2half2_rn(a - __half2float(h.x), b - __half2float(h.y));
}

#define RSTRIDE 80
#define PLANE_B 10240
#define SMEM_H  (3 * 2 * PLANE_B)
#define SMEM_P1 (4 * 2 * PLANE_B)
#define SMEM_P2 (3 * 3 * PLANE_B)

// ===========================================================================
// fp16-accumulator GEMM (q-path / scores / v^T). biasMode: 0=col,1=row,2=none.
// ===========================================================================
__global__ __launch_bounds__(256, 3) void mma_gemm_h(
    const __half* __restrict__ Ah, const __half* __restrict__ Bh,
    const float* __restrict__ bias, int biasMode,
    __half* __restrict__ Ch,
    int ldA, int ldB, int ldC, int K, float alpha,
    long long sA, long long sB, long long sC)
{
    constexpr int NSTG = 3;
    constexpr uint32_t STAGE = 2 * PLANE_B;
    constexpr uint32_t BOFF  = PLANE_B;

    extern __shared__ __align__(16) uint32_t sm[];
    const uint32_t sbase = smem_u32(sm);

    const int bz = blockIdx.z;
    Ah += (long long)bz * sA;
    Bh += (long long)bz * sB;

    const int m0 = blockIdx.y * 128;
    const int n0 = blockIdx.x * 128;
    const int tid  = threadIdx.x;
    const int wid  = tid >> 5, lane = tid & 31;
    const int wm   = wid >> 2, wn = wid & 3;
    const int g    = lane >> 2, t = lane & 3;

    const int lrow = tid >> 1;
    const int lseg = (tid & 1) * 2;
    const char* gAh = (const char*)(Ah + (long long)(m0 + lrow) * ldA) + lseg * 16;
    const char* gBh = (const char*)(Bh + (long long)(n0 + lrow) * ldB) + lseg * 16;
    const uint32_t dst0 = sbase + lrow * RSTRIDE + lseg * 16;

    const uint32_t a_off = (uint32_t)(wm * 64 + (lane & 15)) * RSTRIDE
                         + (uint32_t)(lane >> 4) * 16u;
    const uint32_t b_off = (uint32_t)(wn * 32 + (lane & 7) + ((lane >> 4) & 1) * 8) * RSTRIDE
                         + (uint32_t)((lane >> 3) & 1) * 16u;

    uint32_t acc[4][4][2];
#pragma unroll
    for (int i = 0; i < 4; i++)
#pragma unroll
        for (int j = 0; j < 4; j++) { acc[i][j][0] = 0u; acc[i][j][1] = 0u; }

    const int NCH = K >> 5;

    auto PREF = [&](int chv) {
        const uint32_t so = (uint32_t)(chv % NSTG) * STAGE;
        const long long go = (long long)chv * 64;
        cpa16(dst0 + so,             gAh + go);
        cpa16(dst0 + so + 16,        gAh + go + 16);
        cpa16(dst0 + so + BOFF,      gBh + go);
        cpa16(dst0 + so + BOFF + 16, gBh + go + 16);
    };

    {
        const int npre = (NCH < 2) ? NCH : 2;
        for (int i = 0; i < npre; i++) { PREF(i); CP_COMMIT(); }
    }
    for (int ch = 0; ch < NCH; ch++) {
        const int rem = NCH - 1 - ch;
        if (rem <= 0) CP_WAIT0(); else CP_WAIT1();
        __syncthreads();
        if (ch + 2 < NCH) { PREF(ch + 2); CP_COMMIT(); }

        const uint32_t sb = sbase + (uint32_t)(ch % NSTG) * STAGE;
        const uint32_t aA = sb + a_off;
        const uint32_t aB = sb + BOFF + b_off;
#pragma unroll
        for (int ks = 0; ks < 2; ks++) {
            const uint32_t ko = ks * 32;
            uint32_t bh[4][2];
            ldsm_x4(bh[0][0], bh[0][1], bh[1][0], bh[1][1], aB + ko);
            ldsm_x4(bh[2][0], bh[2][1], bh[3][0], bh[3][1], aB + 16 * RSTRIDE + ko);
#pragma unroll
            for (int mi = 0; mi < 4; mi++) {
                uint32_t ah[4];
                ldsm_x4(ah[0], ah[1], ah[2], ah[3], aA + mi * 16 * RSTRIDE + ko);
#pragma unroll
                for (int ni = 0; ni < 4; ni++)
                    MMA_H16(acc[mi][ni], ah[0], ah[1], ah[2], ah[3],
                            bh[ni][0], bh[ni][1]);
            }
        }
    }

    __half* ChB = Ch + (long long)bz * sC;
    const __half2 alph = __half2half2(__float2half(alpha));
#pragma unroll
    for (int mi = 0; mi < 4; mi++) {
#pragma unroll
        for (int ni = 0; ni < 4; ni++) {
            const int r0 = m0 + wm * 64 + mi * 16 + g;
            const int c  = n0 + wn * 32 + ni * 8 + t * 2;
            __half2 v0 = __hmul2(*(__half2*)&acc[mi][ni][0], alph);
            __half2 v1 = __hmul2(*(__half2*)&acc[mi][ni][1], alph);
            if (biasMode == 0) {
                const __half2 bb = __floats2half2_rn(bias[c], bias[c + 1]);
                v0 = __hadd2(v0, bb);
                v1 = __hadd2(v1, bb);
            } else if (biasMode == 1) {
                v0 = __hadd2(v0, __float2half2_rn(bias[r0]));
                v1 = __hadd2(v1, __float2half2_rn(bias[r0 + 8]));
            }
            ((__half2*)ChB)[((long long)r0 * ldC + c) >> 1]       = v0;
            ((__half2*)ChB)[((long long)(r0 + 8) * ldC + c) >> 1] = v1;
        }
    }
}

// ===========================================================================
// fp32-accumulator GEMM (Mt, att, FFN). OUTM: 0=fp32; 1=fp16 pair; 2=fp16 hi.
// ===========================================================================
template <int NPROD, int OUTM>
__global__ __launch_bounds__(256, 2) void mma_gemm(
    const __half* __restrict__ Ah, const __half* __restrict__ Al,
    const __half* __restrict__ Bh,
    const float* __restrict__ bias,
    float* __restrict__ Cf, __half* __restrict__ Ch, __half* __restrict__ Cl,
    int ldA, int ldB, int ldC, int K, float alpha,
    long long sA, long long sB, long long sC)
{
    constexpr int NSTG = (NPROD == 1) ? 4 : 3;
    constexpr uint32_t STAGE = (NPROD == 1) ? 2 * PLANE_B : 3 * PLANE_B;
    constexpr uint32_t BOFF  = (NPROD == 1) ? PLANE_B : 2 * PLANE_B;

    extern __shared__ __align__(16) uint32_t sm[];
    const uint32_t sbase = smem_u32(sm);

    const int bz = blockIdx.z;
    Ah += (long long)bz * sA;
    if (NPROD >= 2) Al += (long long)bz * sA;
    Bh += (long long)bz * sB;

    const int m0 = blockIdx.y * 128;
    const int n0 = blockIdx.x * 128;
    const int tid  = threadIdx.x;
    const int wid  = tid >> 5, lane = tid & 31;
    const int wm   = wid >> 2, wn = wid & 3;
    const int g    = lane >> 2, t = lane & 3;

    const int lrow = tid >> 1;
    const int lseg = (tid & 1) * 2;
    const char* gAh = (const char*)(Ah + (long long)(m0 + lrow) * ldA) + lseg * 16;
    const char* gAl = (NPROD >= 2)
        ? (const char*)(Al + (long long)(m0 + lrow) * ldA) + lseg * 16 : nullptr;
    const char* gBh = (const char*)(Bh + (long long)(n0 + lrow) * ldB) + lseg * 16;
    const uint32_t dst0 = sbase + lrow * RSTRIDE + lseg * 16;

    const uint32_t a_off = (uint32_t)(wm * 64 + (lane & 15)) * RSTRIDE
                         + (uint32_t)(lane >> 4) * 16u;
    const uint32_t b_off = (uint32_t)(wn * 32 + (lane & 7) + ((lane >> 4) & 1) * 8) * RSTRIDE
                         + (uint32_t)((lane >> 3) & 1) * 16u;

    float acc[4][4][4];
#pragma unroll
    for (int i = 0; i < 4; i++)
#pragma unroll
        for (int j = 0; j < 4; j++)
#pragma unroll
            for (int e = 0; e < 4; e++) acc[i][j][e] = 0.0f;

    const int NCH = K >> 5;

    auto PREF = [&](int chv) {
        const uint32_t so = (uint32_t)(chv % NSTG) * STAGE;
        const long long go = (long long)chv * 64;
        cpa16(dst0 + so,      gAh + go);
        cpa16(dst0 + so + 16, gAh + go + 16);
        if (NPROD >= 2) {
            cpa16(dst0 + so + PLANE_B,      gAl + go);
            cpa16(dst0 + so + PLANE_B + 16, gAl + go + 16);
        }
        cpa16(dst0 + so + BOFF,      gBh + go);
        cpa16(dst0 + so + BOFF + 16, gBh + go + 16);
    };

    auto COMPUTE = [&](int ch) {
        const uint32_t sb = sbase + (uint32_t)(ch % NSTG) * STAGE;
        const uint32_t aA  = sb + a_off;
        const uint32_t aAl = sb + PLANE_B + a_off;
        const uint32_t aB  = sb + BOFF + b_off;
#pragma unroll
        for (int ks = 0; ks < 2; ks++) {
            const uint32_t ko = ks * 32;
            uint32_t bh[4][2];
            ldsm_x4(bh[0][0], bh[0][1], bh[1][0], bh[1][1], aB + ko);
            ldsm_x4(bh[2][0], bh[2][1], bh[3][0], bh[3][1], aB + 16 * RSTRIDE + ko);
#pragma unroll
            for (int mi = 0; mi < 4; mi++) {
                uint32_t ah[4];
                ldsm_x4(ah[0], ah[1], ah[2], ah[3], aA + mi * 16 * RSTRIDE + ko);
#pragma unroll
                for (int ni = 0; ni < 4; ni++)
                    MMA_F16(acc[mi][ni], ah[0], ah[1], ah[2], ah[3], bh[ni][0], bh[ni][1]);
                if (NPROD >= 2) {
                    uint32_t al[4];
                    ldsm_x4(al[0], al[1], al[2], al[3], aAl + mi * 16 * RSTRIDE + ko);
#pragma unroll
                    for (int ni = 0; ni < 4; ni++)
                        MMA_F16(acc[mi][ni], al[0], al[1], al[2], al[3], bh[ni][0], bh[ni][1]);
                }
            }
        }
    };

    {
        const int npre = (NCH < NSTG - 1) ? NCH : (NSTG - 1);
        for (int i = 0; i < npre; i++) { PREF(i); CP_COMMIT(); }
    }
    for (int ch = 0; ch < NCH; ch++) {
        int w = NSTG - 2;
        const int rem = NCH - 1 - ch;
        if (rem < w) w = rem;
        if (w <= 0)      CP_WAIT0();
        else if (w == 1) CP_WAIT1();
        else             CP_WAIT2();
        __syncthreads();
        if (ch + NSTG - 1 < NCH) { PREF(ch + NSTG - 1); CP_COMMIT(); }
        COMPUTE(ch);
    }

    float*  CfB = Cf + (long long)bz * sC;
    __half* ChB = Ch + (long long)bz * sC;
    __half* ClB = Cl + (long long)bz * sC;

#pragma unroll
    for (int mi = 0; mi < 4; mi++) {
#pragma unroll
        for (int ni = 0; ni < 4; ni++) {
            const int r0 = m0 + wm * 64 + mi * 16 + g;
            const int c  = n0 + wn * 32 + ni * 8 + t * 2;
            float v0 = acc[mi][ni][0] * alpha, v1 = acc[mi][ni][1] * alpha;
            float v2 = acc[mi][ni][2] * alpha, v3 = acc[mi][ni][3] * alpha;
            if (bias) {
                const float b0 = bias[c], b1 = bias[c + 1];
                v0 += b0; v1 += b1; v2 += b0; v3 += b1;
            }
            if (OUTM == 0) {
                *(float2*)&CfB[(long long)r0 * ldC + c]       = make_float2(v0, v1);
                *(float2*)&CfB[(long long)(r0 + 8) * ldC + c] = make_float2(v2, v3);
            } else if (OUTM == 1) {
                __half2 h0, l0, h1, l1;
                split2(v0, v1, h0, l0);
                split2(v2, v3, h1, l1);
                ((__half2*)ChB)[((long long)r0 * ldC + c) >> 1]       = h0;
                ((__half2*)ClB)[((long long)r0 * ldC + c) >> 1]       = l0;
                ((__half2*)ChB)[((long long)(r0 + 8) * ldC + c) >> 1] = h1;
                ((__half2*)ClB)[((long long)(r0 + 8) * ldC + c) >> 1] = l1;
            } else {
                ((__half2*)ChB)[((long long)r0 * ldC + c) >> 1]       = __floats2half2_rn(v0, v1);
                ((__half2*)ChB)[((long long)(r0 + 8) * ldC + c) >> 1] = __floats2half2_rn(v2, v3);
            }
        }
    }
}

// ---------------- fp32 -> fp16 ----------------
__global__ __launch_bounds__(256) void tohalf_kernel(
    const float* __restrict__ in, __half* __restrict__ oh, int n4)
{
    const int i = blockIdx.x * 256 + threadIdx.x;
    if (i >= n4) return;
    float4 v = ((const float4*)in)[i];
    ((__half2*)oh)[i * 2]     = __floats2half2_rn(v.x, v.y);
    ((__half2*)oh)[i * 2 + 1] = __floats2half2_rn(v.z, v.w);
}

// ---------------- u = scale * (Wk @ bq) ----------------
__global__ __launch_bounds__(256) void uvec_kernel(
    const float* __restrict__ Wk, const float* __restrict__ bq,
    float* __restrict__ u, float scale)
{
    const int m = blockIdx.x * 256 + threadIdx.x;
    if (m >= 512) return;
    float s = 0.0f;
    for (int n = 0; n < 512; n++) s += Wk[m * 512 + n] * bq[n];
    u[m] = s * scale;
}

// ---------------- c[i] = x_i . u  (one warp per row) ----------------
__device__ __forceinline__ float warpSum(float v) {
#pragma unroll
    for (int o = 16; o > 0; o >>= 1) v += __shfl_xor_sync(0xffffffffu, v, o);
    return v;
}
__device__ __forceinline__ float warpMax(float v) {
#pragma unroll
    for (int o = 16; o > 0; o >>= 1) v = fmaxf(v, __shfl_xor_sync(0xffffffffu, v, o));
    return v;
}

__global__ __launch_bounds__(256) void cvec_kernel(
    const __half* __restrict__ xh, const float* __restrict__ u,
    float* __restrict__ c)
{
    const int warp = (blockIdx.x * 256 + threadIdx.x) >> 5;
    const int lane = threadIdx.x & 31;
    const __half2* xr = (const __half2*)(xh + (long long)warp * 512);
    float s = 0.0f;
#pragma unroll 4
    for (int j = lane; j < 256; j += 32) {
        const __half2 hv = xr[j];
        s += __half2float(hv.x) * u[2 * j] + __half2float(hv.y) * u[2 * j + 1];
    }
    s = warpSum(s);
    if (lane == 0) c[warp] = s;
}

// ------ merged transpose: 4 weights fp32 [512][512] -> fp16 W^T slots ------
__global__ __launch_bounds__(256) void tsplit4_kernel(
    const float* __restrict__ W0, const float* __restrict__ W1,
    const float* __restrict__ W2, const float* __restrict__ W3,
    __half* __restrict__ outBase)
{
    __shared__ float tile[32][33];
    const int z = blockIdx.z;
    const float* in = (z == 0) ? W0 : (z == 1) ? W1 : (z == 2) ? W2 : W3;
    __half* oh = outBase + (long long)z * 512 * 512;
    const int c0 = blockIdx.x * 32, r0 = blockIdx.y * 32;
    const int tx = threadIdx.x & 31, ty = threadIdx.x >> 5;

#pragma unroll
    for (int i = 0; i < 4; i++)
        tile[ty + i * 8][tx] = in[(long long)(r0 + ty + i * 8) * 512 + c0 + tx];
    __syncthreads();
#pragma unroll
    for (int i = 0; i < 4; i++) {
        const float v = tile[tx][ty + i * 8];
        oh[(long long)(c0 + ty + i * 8) * 512 + r0 + tx] = __float2half_rn(v);
    }
}

// -------- softmax, in-place, logits += c[col] --------
__global__ __launch_bounds__(256) void softmax_kernel(
    __half* __restrict__ H, const float* __restrict__ c)
{
    const long long base = (long long)blockIdx.x * 2048;
    const float* cb = c + (long long)(blockIdx.x >> 11) * 2048;
    __half2* rh = (__half2*)(H + base);
    const int tid = threadIdx.x;
    const int lane = tid & 31, wid = tid >> 5;
    __shared__ float sh[8];

    float v[8];
#pragma unroll
    for (int j = 0; j < 4; j++) {
        const __half2 hv = rh[tid * 4 + j];
        v[2*j]   = __half2float(hv.x) + cb[tid * 8 + 2 * j];
        v[2*j+1] = __half2float(hv.y) + cb[tid * 8 + 2 * j + 1];
    }

    float m = v[0];
#pragma unroll
    for (int i = 1; i < 8; i++) m = fmaxf(m, v[i]);
    m = warpMax(m);
    if (lane == 0) sh[wid] = m;
    __syncthreads();
    m = sh[0];
#pragma unroll
    for (int w = 1; w < 8; w++) m = fmaxf(m, sh[w]);

    float e[8];
    float s = 0.0f;
#pragma unroll
    for (int i = 0; i < 8; i++) { e[i] = __expf(v[i] - m); s += e[i]; }
    s = warpSum(s);
    __syncthreads();
    if (lane == 0) sh[wid] = s;
    __syncthreads();
    float tot = 0.0f;
#pragma unroll
    for (int w = 0; w < 8; w++) tot += sh[w];
    const float inv = 1.0f / tot;

#pragma unroll
    for (int j = 0; j < 4; j++)
        rh[tid * 4 + j] = __floats2half2_rn(e[2*j] * inv, e[2*j+1] * inv);
}

// ---------------- fused add(+gelu)+LN, vectorized fp16-pair I/O ----------------
template <int MODE, bool XPAIR, bool YPAIR>
__global__ __launch_bounds__(128) void rowln_kernel(
    const float* __restrict__ Xf,
    const __half* __restrict__ Xh, const __half* __restrict__ Xl,
    const __half* __restrict__ Yh, const __half* __restrict__ Yl,
    const float* __restrict__ g, const float* __restrict__ b,
    __half* __restrict__ Oh, __half* __restrict__ Ol)
{
    const long long row = (long long)blockIdx.x * 512;
    const int tid = threadIdx.x;
    const int lane = tid & 31, wid = tid >> 5;
    const int c0 = tid * 4;
    __shared__ float s1[4], s2[4];

    float t[4];
    {
        float xv[4];
        if (XPAIR) {
            const __half2 xh0 = ((const __half2*)(Xh + row + c0))[0];
            const __half2 xh1 = ((const __half2*)(Xh + row + c0))[1];
            const __half2 xl0 = ((const __half2*)(Xl + row + c0))[0];
            const __half2 xl1 = ((const __half2*)(Xl + row + c0))[1];
            xv[0] = __half2float(xh0.x) + __half2float(xl0.x);
            xv[1] = __half2float(xh0.y) + __half2float(xl0.y);
            xv[2] = __half2float(xh1.x) + __half2float(xl1.x);
            xv[3] = __half2float(xh1.y) + __half2float(xl1.y);
        } else {
            const float4 xf = *(const float4*)(Xf + row + c0);
            xv[0] = xf.x; xv[1] = xf.y; xv[2] = xf.z; xv[3] = xf.w;
        }
        const __half2 yh0 = ((const __half2*)(Yh + row + c0))[0];
        const __half2 yh1 = ((const __half2*)(Yh + row + c0))[1];
        t[0] = xv[0] + __half2float(yh0.x);
        t[1] = xv[1] + __half2float(yh0.y);
        t[2] = xv[2] + __half2float(yh1.x);
        t[3] = xv[3] + __half2float(yh1.y);
        if (YPAIR) {
            const __half2 yl0 = ((const __half2*)(Yl + row + c0))[0];
            const __half2 yl1 = ((const __half2*)(Yl + row + c0))[1];
            t[0] += __half2float(yl0.x);
            t[1] += __half2float(yl0.y);
            t[2] += __half2float(yl1.x);
            t[3] += __half2float(yl1.y);
        }
    }
    float sum = 0.0f, sq = 0.0f;
#pragma unroll
    for (int i = 0; i < 4; i++) {
        if (MODE == 1)
            t[i] = 0.5f * t[i] * (1.0f + erff(t[i] * 0.7071067811865476f));
        sum += t[i];
        sq += t[i] * t[i];
    }
    sum = warpSum(sum);
    sq = warpSum(sq);
    if (lane == 0) { s1[wid] = sum; s2[wid] = sq; }
    __syncthreads();
    float ts = 0.0f, tq = 0.0f;
#pragma unroll
    for (int w = 0; w < 4; w++) { ts += s1[w]; tq += s2[w]; }
    const float mean = ts * (1.0f / 512.0f);
    const float var = tq * (1.0f / 512.0f) - mean * mean;
    const float inv = rsqrtf(var + 1e-5f);

    const float4 gv = *(const float4*)(g + c0);
    const float4 bv = *(const float4*)(b + c0);
    float o[4];
    o[0] = (t[0] - mean) * inv * gv.x + bv.x;
    o[1] = (t[1] - mean) * inv * gv.y + bv.y;
    o[2] = (t[2] - mean) * inv * gv.z + bv.z;
    o[3] = (t[3] - mean) * inv * gv.w + bv.w;
    __half2 h0, l0, h1, l1;
    split2(o[0], o[1], h0, l0);
    split2(o[2], o[3], h1, l1);
    ((__half2*)(Oh + row + c0))[0] = h0;
    ((__half2*)(Oh + row + c0))[1] = h1;
    ((__half2*)(Ol + row + c0))[0] = l0;
    ((__half2*)(Ol + row + c0))[1] = l1;
}

// ---------------- host ----------------
template <typename T>
static T* symaddr(const void* sym)
{
    void* p = nullptr;
    cudaGetSymbolAddress(&p, sym);
    return (T*)p;
}

extern "C" void kernel_launch(void* const* d_in, const int* in_sizes, int n_in,
                              void* d_out, int out_size)
{
    const float* x    = (const float*)d_in[0];
    const float* Wq   = (const float*)d_in[1];
    const float* bq   = (const float*)d_in[2];
    const float* Wk   = (const float*)d_in[3];
    const float* bk   = (const float*)d_in[4];
    const float* Wv   = (const float*)d_in[5];
    const float* bv   = (const float*)d_in[6];
    const float* ln0g = (const float*)d_in[7];
    const float* ln0b = (const float*)d_in[8];
    const float* W1   = (const float*)d_in[9];
    const float* b1   = (const float*)d_in[10];
    const float* ln1g = (const float*)d_in[11];
    const float* ln1b = (const float*)d_in[12];
    const float* W2   = (const float*)d_in[13];
    const float* b2   = (const float*)d_in[14];
    const float* ln2g = (const float*)d_in[15];
    const float* ln2b = (const float*)d_in[16];
    const float* W3   = (const float*)d_in[17];
    const float* b3   = (const float*)d_in[18];
    float* out = (float*)d_out;

    __half* xh  = symaddr<__half>(g_xh);
    __half* yh  = symaddr<__half>(g_yh);
    __half* vth = symaddr<__half>(g_vth);
    __half* ath = symaddr<__half>(g_ath);
    __half* onh = symaddr<__half>(g_onh);  __half* onl = symaddr<__half>(g_onl);
    __half* th  = symaddr<__half>(g_th);   __half* tl  = symaddr<__half>(g_tl);
    __half* hh  = symaddr<__half>(g_hh);   __half* hl  = symaddr<__half>(g_hl);
    __half* h2h = symaddr<__half>(g_h2h);  __half* h2l = symaddr<__half>(g_h2l);
    __half* sh_ = symaddr<__half>(g_sh);
    __half* wth = symaddr<__half>(g_wth);
    __half* wqh = symaddr<__half>(g_wqh);
    __half* wkh = symaddr<__half>(g_wkh);
    float* u  = symaddr<float>(g_u);
    float* c  = symaddr<float>(g_c);

    cudaFuncSetAttribute(mma_gemm_h,    cudaFuncAttributeMaxDynamicSharedMemorySize, SMEM_H);
    cudaFuncSetAttribute(mma_gemm<1,2>, cudaFuncAttributeMaxDynamicSharedMemorySize, SMEM_P1);
    cudaFuncSetAttribute(mma_gemm<2,0>, cudaFuncAttributeMaxDynamicSharedMemorySize, SMEM_P2);
    cudaFuncSetAttribute(mma_gemm<2,1>, cudaFuncAttributeMaxDynamicSharedMemorySize, SMEM_P2);

    const long long sSD = 2048LL * 512;
    const long long sSS = 2048LL * 2048;
    const long long WSZ = 512LL * 512;
    const float scale = 0.044194173824159216f;   // 1/sqrt(512)

    dim3 gProj(4, 128, 1);
    dim3 gScores(16, 16, 8);
    dim3 gVt(128, 4, 1);
    dim3 gAtt(4, 16, 8);

    // 1-4: inputs for M path
    tohalf_kernel<<<MTOT / 1024, 256>>>(x, xh, MTOT / 4);
    tohalf_kernel<<<256, 256>>>(Wq, wqh, 65536);
    tohalf_kernel<<<256, 256>>>(Wk, wkh, 65536);
    uvec_kernel<<<2, 256>>>(Wk, bq, u, scale);

    // 5: Mt = scale * Wk @ Wq^T  (B-operand for y GEMM), fp32 acc
    mma_gemm<1,2><<<dim3(4, 4, 1), 256, SMEM_P1>>>(wkh, nullptr, wqh,
        nullptr, nullptr, wth, nullptr, 512, 512, 512, 512, scale, 0, 0, 0);

    // 6: y = x @ M  (ncu profiles this launch)
    mma_gemm_h<<<gProj, 256, SMEM_H>>>(xh, wth,
        nullptr, 2, yh, 512, 512, 512, 512, 1.0f, 0, 0, 0);

    // 7: c[i] = x_i . u
    cvec_kernel<<<2048, 256>>>(xh, u, c);

    // 8: scores = y @ x^T (fp16 acc)
    mma_gemm_h<<<gScores, 256, SMEM_H>>>(yh, xh,
        nullptr, 2, sh_, 512, 512, 2048, 512, 1.0f, sSD, sSD, sSS);

    // 9: softmax (+c) in-place
    softmax_kernel<<<16384, 256>>>(sh_, c);

    // 10: merged weight transposes (Wv,W1,W2,W3 -> slots 2..5)
    tsplit4_kernel<<<dim3(16, 16, 4), 256>>>(Wv, W1, W2, W3, wth + 2 * WSZ);

    // 11: v^T = Wv^T @ x^T (row bias bv)
    mma_gemm_h<<<gVt, 256, SMEM_H>>>(wth + 2 * WSZ, xh,
        bv, 1, vth, 512, 512, 16384, 512, 1.0f, 0, 0, 0);

    // 12: att = w @ v (fp32 acc) -> fp16 hi
    mma_gemm<1,2><<<gAtt, 256, SMEM_P1>>>(sh_, nullptr, vth,
        nullptr, nullptr, ath, nullptr, 2048, 16384, 512, 2048, 1.0f,
        sSS, 2048, sSD);

    // 13: out_nxt = LN(x + att)
    rowln_kernel<0, false, false><<<16384, 128>>>(
        x, nullptr, nullptr, ath, nullptr, ln0g, ln0b, onh, onl);

    // 14-15: h1
    mma_gemm<2,1><<<gProj, 256, SMEM_P2>>>(onh, onl, wth + 3 * WSZ,
        b1, nullptr, th, tl, 512, 512, 512, 512, 1.0f, 0, 0, 0);
    rowln_kernel<1, true, true><<<16384, 128>>>(
        nullptr, onh, onl, th, tl, ln1g, ln1b, hh, hl);

    // 16-17: h2
    mma_gemm<2,1><<<gProj, 256, SMEM_P2>>>(hh, hl, wth + 4 * WSZ,
        b2, nullptr, th, tl, 512, 512, 512, 512, 1.0f, 0, 0, 0);
    rowln_kernel<1, true, true><<<16384, 128>>>(
        nullptr, onh, onl, th, tl, ln2g, ln2b, h2h, h2l);

    // 18: out = h2 @ W3 + b3 (fp32)
    mma_gemm<2,0><<<gProj, 256, SMEM_P2>>>(h2h, h2l, wth + 5 * WSZ,
        b3, out, nullptr, nullptr, 512, 512, 512, 512, 1.0f, 0, 0, 0);
}

// round 14
// speedup vs baseline: 1.0916x; 1.0916x over previous
#include <cuda_runtime.h>
#include <cuda_fp16.h>
#include <math.h>
#include <stdint.h>

// ===========================================================================
// AttentionBlock B=8,S=2048,D=512 — mma.sync fp16, precision-tiered GEMMs
// R14: R13 (k-path eliminated via M = scale*(Wq Wk^T)) with uvec_kernel
//      fixed (one warp per row, coalesced).
// ===========================================================================

#define MTOT (16384 * 512)
__device__ __half g_xh[MTOT];
__device__ __half g_yh[MTOT];                       // y = x @ M
__device__ __half g_vth[MTOT];                      // v^T [512][16384]
__device__ __half g_ath[MTOT];                      // att fp16
__device__ __half g_onh[MTOT], g_onl[MTOT];
__device__ __half g_th[MTOT],  g_tl[MTOT];
__device__ __half g_hh[MTOT],  g_hl[MTOT];
__device__ __half g_h2h[MTOT], g_h2l[MTOT];
__device__ __half g_sh[8LL * 2048 * 2048];
__device__ __half g_wth[6 * 512 * 512];             // slot0=Mt, 2..5 = Wv,W1,W2,W3 ^T
__device__ __half g_wqh[512 * 512], g_wkh[512 * 512];
__device__ float g_u[512];
__device__ float g_c[16384];

// ---------------- helpers ----------------
__device__ __forceinline__ uint32_t smem_u32(const void* p) {
    uint32_t a;
    asm("{ .reg .u64 t; cvta.to.shared.u64 t, %1; cvt.u32.u64 %0, t; }"
        : "=r"(a) : "l"(p));
    return a;
}
__device__ __forceinline__ void cpa16(uint32_t dst, const void* src) {
    asm volatile("cp.async.cg.shared.global [%0], [%1], 16;"
                 :: "r"(dst), "l"(src) : "memory");
}
#define CP_COMMIT() asm volatile("cp.async.commit_group;" ::: "memory")
#define CP_WAIT0()  asm volatile("cp.async.wait_group 0;"  ::: "memory")
#define CP_WAIT1()  asm volatile("cp.async.wait_group 1;"  ::: "memory")
#define CP_WAIT2()  asm volatile("cp.async.wait_group 2;"  ::: "memory")

#define MMA_F16(c, a0, a1, a2, a3, b0, b1)                                    \
    asm volatile("mma.sync.aligned.m16n8k16.row.col.f32.f16.f16.f32 "         \
        "{%0,%1,%2,%3}, {%4,%5,%6,%7}, {%8,%9}, {%0,%1,%2,%3};"               \
        : "+f"((c)[0]), "+f"((c)[1]), "+f"((c)[2]), "+f"((c)[3])              \
        : "r"(a0), "r"(a1), "r"(a2), "r"(a3), "r"(b0), "r"(b1))

#define MMA_H16(c, a0, a1, a2, a3, b0, b1)                                    \
    asm volatile("mma.sync.aligned.m16n8k16.row.col.f16.f16.f16.f16 "         \
        "{%0,%1}, {%2,%3,%4,%5}, {%6,%7}, {%0,%1};"                           \
        : "+r"((c)[0]), "+r"((c)[1])                                          \
        : "r"(a0), "r"(a1), "r"(a2), "r"(a3), "r"(b0), "r"(b1))

__device__ __forceinline__ void ldsm_x4(uint32_t& r0, uint32_t& r1,
                                        uint32_t& r2, uint32_t& r3, uint32_t a) {
    asm volatile("ldmatrix.sync.aligned.m8n8.x4.shared.b16 {%0,%1,%2,%3}, [%4];"
                 : "=r"(r0), "=r"(r1), "=r"(r2), "=r"(r3) : "r"(a));
}

__device__ __forceinline__ void split2(float a, float b, __half2& h, __half2& l) {
    h = __floats2half2_rn(a, b);
    l = __floats2half2_rn(a - __half2float(h.x), b - __half2float(h.y));
}

#define RSTRIDE 80
#define PLANE_B 10240
#define SMEM_H  (3 * 2 * PLANE_B)
#define SMEM_P1 (4 * 2 * PLANE_B)
#define SMEM_P2 (3 * 3 * PLANE_B)

// ===========================================================================
// fp16-accumulator GEMM. biasMode: 0=col, 1=row, 2=none.
// ===========================================================================
__global__ __launch_bounds__(256, 3) void mma_gemm_h(
    const __half* __restrict__ Ah, const __half* __restrict__ Bh,
    const float* __restrict__ bias, int biasMode,
    __half* __restrict__ Ch,
    int ldA, int ldB, int ldC, int K, float alpha,
    long long sA, long long sB, long long sC)
{
    constexpr int NSTG = 3;
    constexpr uint32_t STAGE = 2 * PLANE_B;
    constexpr uint32_t BOFF  = PLANE_B;

    extern __shared__ __align__(16) uint32_t sm[];
    const uint32_t sbase = smem_u32(sm);

    const int bz = blockIdx.z;
    Ah += (long long)bz * sA;
    Bh += (long long)bz * sB;

    const int m0 = blockIdx.y * 128;
    const int n0 = blockIdx.x * 128;
    const int tid  = threadIdx.x;
    const int wid  = tid >> 5, lane = tid & 31;
    const int wm   = wid >> 2, wn = wid & 3;
    const int g    = lane >> 2, t = lane & 3;

    const int lrow = tid >> 1;
    const int lseg = (tid & 1) * 2;
    const char* gAh = (const char*)(Ah + (long long)(m0 + lrow) * ldA) + lseg * 16;
    const char* gBh = (const char*)(Bh + (long long)(n0 + lrow) * ldB) + lseg * 16;
    const uint32_t dst0 = sbase + lrow * RSTRIDE + lseg * 16;

    const uint32_t a_off = (uint32_t)(wm * 64 + (lane & 15)) * RSTRIDE
                         + (uint32_t)(lane >> 4) * 16u;
    const uint32_t b_off = (uint32_t)(wn * 32 + (lane & 7) + ((lane >> 4) & 1) * 8) * RSTRIDE
                         + (uint32_t)((lane >> 3) & 1) * 16u;

    uint32_t acc[4][4][2];
#pragma unroll
    for (int i = 0; i < 4; i++)
#pragma unroll
        for (int j = 0; j < 4; j++) { acc[i][j][0] = 0u; acc[i][j][1] = 0u; }

    const int NCH = K >> 5;

    auto PREF = [&](int chv) {
        const uint32_t so = (uint32_t)(chv % NSTG) * STAGE;
        const long long go = (long long)chv * 64;
        cpa16(dst0 + so,             gAh + go);
        cpa16(dst0 + so + 16,        gAh + go + 16);
        cpa16(dst0 + so + BOFF,      gBh + go);
        cpa16(dst0 + so + BOFF + 16, gBh + go + 16);
    };

    {
        const int npre = (NCH < 2) ? NCH : 2;
        for (int i = 0; i < npre; i++) { PREF(i); CP_COMMIT(); }
    }
    for (int ch = 0; ch < NCH; ch++) {
        const int rem = NCH - 1 - ch;
        if (rem <= 0) CP_WAIT0(); else CP_WAIT1();
        __syncthreads();
        if (ch + 2 < NCH) { PREF(ch + 2); CP_COMMIT(); }

        const uint32_t sb = sbase + (uint32_t)(ch % NSTG) * STAGE;
        const uint32_t aA = sb + a_off;
        const uint32_t aB = sb + BOFF + b_off;
#pragma unroll
        for (int ks = 0; ks < 2; ks++) {
            const uint32_t ko = ks * 32;
            uint32_t bh[4][2];
            ldsm_x4(bh[0][0], bh[0][1], bh[1][0], bh[1][1], aB + ko);
            ldsm_x4(bh[2][0], bh[2][1], bh[3][0], bh[3][1], aB + 16 * RSTRIDE + ko);
#pragma unroll
            for (int mi = 0; mi < 4; mi++) {
                uint32_t ah[4];
                ldsm_x4(ah[0], ah[1], ah[2], ah[3], aA + mi * 16 * RSTRIDE + ko);
#pragma unroll
                for (int ni = 0; ni < 4; ni++)
                    MMA_H16(acc[mi][ni], ah[0], ah[1], ah[2], ah[3],
                            bh[ni][0], bh[ni][1]);
            }
        }
    }

    __half* ChB = Ch + (long long)bz * sC;
    const __half2 alph = __half2half2(__float2half(alpha));
#pragma unroll
    for (int mi = 0; mi < 4; mi++) {
#pragma unroll
        for (int ni = 0; ni < 4; ni++) {
            const int r0 = m0 + wm * 64 + mi * 16 + g;
            const int c  = n0 + wn * 32 + ni * 8 + t * 2;
            __half2 v0 = __hmul2(*(__half2*)&acc[mi][ni][0], alph);
            __half2 v1 = __hmul2(*(__half2*)&acc[mi][ni][1], alph);
            if (biasMode == 0) {
                const __half2 bb = __floats2half2_rn(bias[c], bias[c + 1]);
                v0 = __hadd2(v0, bb);
                v1 = __hadd2(v1, bb);
            } else if (biasMode == 1) {
                v0 = __hadd2(v0, __float2half2_rn(bias[r0]));
                v1 = __hadd2(v1, __float2half2_rn(bias[r0 + 8]));
            }
            ((__half2*)ChB)[((long long)r0 * ldC + c) >> 1]       = v0;
            ((__half2*)ChB)[((long long)(r0 + 8) * ldC + c) >> 1] = v1;
        }
    }
}

// ===========================================================================
// fp32-accumulator GEMM. OUTM: 0=fp32; 1=fp16 pair; 2=fp16 hi.
// ===========================================================================
template <int NPROD, int OUTM>
__global__ __launch_bounds__(256, 2) void mma_gemm(
    const __half* __restrict__ Ah, const __half* __restrict__ Al,
    const __half* __restrict__ Bh,
    const float* __restrict__ bias,
    float* __restrict__ Cf, __half* __restrict__ Ch, __half* __restrict__ Cl,
    int ldA, int ldB, int ldC, int K, float alpha,
    long long sA, long long sB, long long sC)
{
    constexpr int NSTG = (NPROD == 1) ? 4 : 3;
    constexpr uint32_t STAGE = (NPROD == 1) ? 2 * PLANE_B : 3 * PLANE_B;
    constexpr uint32_t BOFF  = (NPROD == 1) ? PLANE_B : 2 * PLANE_B;

    extern __shared__ __align__(16) uint32_t sm[];
    const uint32_t sbase = smem_u32(sm);

    const int bz = blockIdx.z;
    Ah += (long long)bz * sA;
    if (NPROD >= 2) Al += (long long)bz * sA;
    Bh += (long long)bz * sB;

    const int m0 = blockIdx.y * 128;
    const int n0 = blockIdx.x * 128;
    const int tid  = threadIdx.x;
    const int wid  = tid >> 5, lane = tid & 31;
    const int wm   = wid >> 2, wn = wid & 3;
    const int g    = lane >> 2, t = lane & 3;

    const int lrow = tid >> 1;
    const int lseg = (tid & 1) * 2;
    const char* gAh = (const char*)(Ah + (long long)(m0 + lrow) * ldA) + lseg * 16;
    const char* gAl = (NPROD >= 2)
        ? (const char*)(Al + (long long)(m0 + lrow) * ldA) + lseg * 16 : nullptr;
    const char* gBh = (const char*)(Bh + (long long)(n0 + lrow) * ldB) + lseg * 16;
    const uint32_t dst0 = sbase + lrow * RSTRIDE + lseg * 16;

    const uint32_t a_off = (uint32_t)(wm * 64 + (lane & 15)) * RSTRIDE
                         + (uint32_t)(lane >> 4) * 16u;
    const uint32_t b_off = (uint32_t)(wn * 32 + (lane & 7) + ((lane >> 4) & 1) * 8) * RSTRIDE
                         + (uint32_t)((lane >> 3) & 1) * 16u;

    float acc[4][4][4];
#pragma unroll
    for (int i = 0; i < 4; i++)
#pragma unroll
        for (int j = 0; j < 4; j++)
#pragma unroll
            for (int e = 0; e < 4; e++) acc[i][j][e] = 0.0f;

    const int NCH = K >> 5;

    auto PREF = [&](int chv) {
        const uint32_t so = (uint32_t)(chv % NSTG) * STAGE;
        const long long go = (long long)chv * 64;
        cpa16(dst0 + so,      gAh + go);
        cpa16(dst0 + so + 16, gAh + go + 16);
        if (NPROD >= 2) {
            cpa16(dst0 + so + PLANE_B,      gAl + go);
            cpa16(dst0 + so + PLANE_B + 16, gAl + go + 16);
        }
        cpa16(dst0 + so + BOFF,      gBh + go);
        cpa16(dst0 + so + BOFF + 16, gBh + go + 16);
    };

    auto COMPUTE = [&](int ch) {
        const uint32_t sb = sbase + (uint32_t)(ch % NSTG) * STAGE;
        const uint32_t aA  = sb + a_off;
        const uint32_t aAl = sb + PLANE_B + a_off;
        const uint32_t aB  = sb + BOFF + b_off;
#pragma unroll
        for (int ks = 0; ks < 2; ks++) {
            const uint32_t ko = ks * 32;
            uint32_t bh[4][2];
            ldsm_x4(bh[0][0], bh[0][1], bh[1][0], bh[1][1], aB + ko);
            ldsm_x4(bh[2][0], bh[2][1], bh[3][0], bh[3][1], aB + 16 * RSTRIDE + ko);
#pragma unroll
            for (int mi = 0; mi < 4; mi++) {
                uint32_t ah[4];
                ldsm_x4(ah[0], ah[1], ah[2], ah[3], aA + mi * 16 * RSTRIDE + ko);
#pragma unroll
                for (int ni = 0; ni < 4; ni++)
                    MMA_F16(acc[mi][ni], ah[0], ah[1], ah[2], ah[3], bh[ni][0], bh[ni][1]);
                if (NPROD >= 2) {
                    uint32_t al[4];
                    ldsm_x4(al[0], al[1], al[2], al[3], aAl + mi * 16 * RSTRIDE + ko);
#pragma unroll
                    for (int ni = 0; ni < 4; ni++)
                        MMA_F16(acc[mi][ni], al[0], al[1], al[2], al[3], bh[ni][0], bh[ni][1]);
                }
            }
        }
    };

    {
        const int npre = (NCH < NSTG - 1) ? NCH : (NSTG - 1);
        for (int i = 0; i < npre; i++) { PREF(i); CP_COMMIT(); }
    }
    for (int ch = 0; ch < NCH; ch++) {
        int w = NSTG - 2;
        const int rem = NCH - 1 - ch;
        if (rem < w) w = rem;
        if (w <= 0)      CP_WAIT0();
        else if (w == 1) CP_WAIT1();
        else             CP_WAIT2();
        __syncthreads();
        if (ch + NSTG - 1 < NCH) { PREF(ch + NSTG - 1); CP_COMMIT(); }
        COMPUTE(ch);
    }

    float*  CfB = Cf + (long long)bz * sC;
    __half* ChB = Ch + (long long)bz * sC;
    __half* ClB = Cl + (long long)bz * sC;

#pragma unroll
    for (int mi = 0; mi < 4; mi++) {
#pragma unroll
        for (int ni = 0; ni < 4; ni++) {
            const int r0 = m0 + wm * 64 + mi * 16 + g;
            const int c  = n0 + wn * 32 + ni * 8 + t * 2;
            float v0 = acc[mi][ni][0] * alpha, v1 = acc[mi][ni][1] * alpha;
            float v2 = acc[mi][ni][2] * alpha, v3 = acc[mi][ni][3] * alpha;
            if (bias) {
                const float b0 = bias[c], b1 = bias[c + 1];
                v0 += b0; v1 += b1; v2 += b0; v3 += b1;
            }
            if (OUTM == 0) {
                *(float2*)&CfB[(long long)r0 * ldC + c]       = make_float2(v0, v1);
                *(float2*)&CfB[(long long)(r0 + 8) * ldC + c] = make_float2(v2, v3);
            } else if (OUTM == 1) {
                __half2 h0, l0, h1, l1;
                split2(v0, v1, h0, l0);
                split2(v2, v3, h1, l1);
                ((__half2*)ChB)[((long long)r0 * ldC + c) >> 1]       = h0;
                ((__half2*)ClB)[((long long)r0 * ldC + c) >> 1]       = l0;
                ((__half2*)ChB)[((long long)(r0 + 8) * ldC + c) >> 1] = h1;
                ((__half2*)ClB)[((long long)(r0 + 8) * ldC + c) >> 1] = l1;
            } else {
                ((__half2*)ChB)[((long long)r0 * ldC + c) >> 1]       = __floats2half2_rn(v0, v1);
                ((__half2*)ChB)[((long long)(r0 + 8) * ldC + c) >> 1] = __floats2half2_rn(v2, v3);
            }
        }
    }
}

// ---------------- fp32 -> fp16 ----------------
__global__ __launch_bounds__(256) void tohalf_kernel(
    const float* __restrict__ in, __half* __restrict__ oh, int n4)
{
    const int i = blockIdx.x * 256 + threadIdx.x;
    if (i >= n4) return;
    float4 v = ((const float4*)in)[i];
    ((__half2*)oh)[i * 2]     = __floats2half2_rn(v.x, v.y);
    ((__half2*)oh)[i * 2 + 1] = __floats2half2_rn(v.z, v.w);
}

// -------- warp reductions --------
__device__ __forceinline__ float warpSum(float v) {
#pragma unroll
    for (int o = 16; o > 0; o >>= 1) v += __shfl_xor_sync(0xffffffffu, v, o);
    return v;
}
__device__ __forceinline__ float warpMax(float v) {
#pragma unroll
    for (int o = 16; o > 0; o >>= 1) v = fmaxf(v, __shfl_xor_sync(0xffffffffu, v, o));
    return v;
}

// ---------------- u = scale * (Wk @ bq): one warp per row, coalesced -------
__global__ __launch_bounds__(256) void uvec_kernel(
    const float* __restrict__ Wk, const float* __restrict__ bq,
    float* __restrict__ u, float scale)
{
    const int row = blockIdx.x * 8 + (threadIdx.x >> 5);
    const int lane = threadIdx.x & 31;
    const float* wr = Wk + (long long)row * 512;
    float s = 0.0f;
#pragma unroll 4
    for (int j = lane; j < 512; j += 32) s += wr[j] * bq[j];
    s = warpSum(s);
    if (lane == 0) u[row] = s * scale;
}

// ---------------- c[i] = x_i . u  (one warp per row) ----------------
__global__ __launch_bounds__(256) void cvec_kernel(
    const __half* __restrict__ xh, const float* __restrict__ u,
    float* __restrict__ c)
{
    const int warp = (blockIdx.x * 256 + threadIdx.x) >> 5;
    const int lane = threadIdx.x & 31;
    const __half2* xr = (const __half2*)(xh + (long long)warp * 512);
    float s = 0.0f;
#pragma unroll 4
    for (int j = lane; j < 256; j += 32) {
        const __half2 hv = xr[j];
        s += __half2float(hv.x) * u[2 * j] + __half2float(hv.y) * u[2 * j + 1];
    }
    s = warpSum(s);
    if (lane == 0) c[warp] = s;
}

// ------ merged transpose: 4 weights fp32 [512][512] -> fp16 W^T slots ------
__global__ __launch_bounds__(256) void tsplit4_kernel(
    const float* __restrict__ W0, const float* __restrict__ W1,
    const float* __restrict__ W2, const float* __restrict__ W3,
    __half* __restrict__ outBase)
{
    __shared__ float tile[32][33];
    const int z = blockIdx.z;
    const float* in = (z == 0) ? W0 : (z == 1) ? W1 : (z == 2) ? W2 : W3;
    __half* oh = outBase + (long long)z * 512 * 512;
    const int c0 = blockIdx.x * 32, r0 = blockIdx.y * 32;
    const int tx = threadIdx.x & 31, ty = threadIdx.x >> 5;

#pragma unroll
    for (int i = 0; i < 4; i++)
        tile[ty + i * 8][tx] = in[(long long)(r0 + ty + i * 8) * 512 + c0 + tx];
    __syncthreads();
#pragma unroll
    for (int i = 0; i < 4; i++) {
        const float v = tile[tx][ty + i * 8];
        oh[(long long)(c0 + ty + i * 8) * 512 + r0 + tx] = __float2half_rn(v);
    }
}

// -------- softmax, in-place, logits += c[col] --------
__global__ __launch_bounds__(256) void softmax_kernel(
    __half* __restrict__ H, const float* __restrict__ c)
{
    const long long base = (long long)blockIdx.x * 2048;
    const float* cb = c + (long long)(blockIdx.x >> 11) * 2048;
    __half2* rh = (__half2*)(H + base);
    const int tid = threadIdx.x;
    const int lane = tid & 31, wid = tid >> 5;
    __shared__ float sh[8];

    float v[8];
#pragma unroll
    for (int j = 0; j < 4; j++) {
        const __half2 hv = rh[tid * 4 + j];
        v[2*j]   = __half2float(hv.x) + cb[tid * 8 + 2 * j];
        v[2*j+1] = __half2float(hv.y) + cb[tid * 8 + 2 * j + 1];
    }

    float m = v[0];
#pragma unroll
    for (int i = 1; i < 8; i++) m = fmaxf(m, v[i]);
    m = warpMax(m);
    if (lane == 0) sh[wid] = m;
    __syncthreads();
    m = sh[0];
#pragma unroll
    for (int w = 1; w < 8; w++) m = fmaxf(m, sh[w]);

    float e[8];
    float s = 0.0f;
#pragma unroll
    for (int i = 0; i < 8; i++) { e[i] = __expf(v[i] - m); s += e[i]; }
    s = warpSum(s);
    __syncthreads();
    if (lane == 0) sh[wid] = s;
    __syncthreads();
    float tot = 0.0f;
#pragma unroll
    for (int w = 0; w < 8; w++) tot += sh[w];
    const float inv = 1.0f / tot;

#pragma unroll
    for (int j = 0; j < 4; j++)
        rh[tid * 4 + j] = __floats2half2_rn(e[2*j] * inv, e[2*j+1] * inv);
}

// ---------------- fused add(+gelu)+LN, vectorized fp16-pair I/O ------------
template <int MODE, bool XPAIR, bool YPAIR>
__global__ __launch_bounds__(128) void rowln_kernel(
    const float* __restrict__ Xf,
    const __half* __restrict__ Xh, const __half* __restrict__ Xl,
    const __half* __restrict__ Yh, const __half* __restrict__ Yl,
    const float* __restrict__ g, const float* __restrict__ b,
    __half* __restrict__ Oh, __half* __restrict__ Ol)
{
    const long long row = (long long)blockIdx.x * 512;
    const int tid = threadIdx.x;
    const int lane = tid & 31, wid = tid >> 5;
    const int c0 = tid * 4;
    __shared__ float s1[4], s2[4];

    float t[4];
    {
        float xv[4];
        if (XPAIR) {
            const __half2 xh0 = ((const __half2*)(Xh + row + c0))[0];
            const __half2 xh1 = ((const __half2*)(Xh + row + c0))[1];
            const __half2 xl0 = ((const __half2*)(Xl + row + c0))[0];
            const __half2 xl1 = ((const __half2*)(Xl + row + c0))[1];
            xv[0] = __half2float(xh0.x) + __half2float(xl0.x);
            xv[1] = __half2float(xh0.y) + __half2float(xl0.y);
            xv[2] = __half2float(xh1.x) + __half2float(xl1.x);
            xv[3] = __half2float(xh1.y) + __half2float(xl1.y);
        } else {
            const float4 xf = *(const float4*)(Xf + row + c0);
            xv[0] = xf.x; xv[1] = xf.y; xv[2] = xf.z; xv[3] = xf.w;
        }
        const __half2 yh0 = ((const __half2*)(Yh + row + c0))[0];
        const __half2 yh1 = ((const __half2*)(Yh + row + c0))[1];
        t[0] = xv[0] + __half2float(yh0.x);
        t[1] = xv[1] + __half2float(yh0.y);
        t[2] = xv[2] + __half2float(yh1.x);
        t[3] = xv[3] + __half2float(yh1.y);
        if (YPAIR) {
            const __half2 yl0 = ((const __half2*)(Yl + row + c0))[0];
            const __half2 yl1 = ((const __half2*)(Yl + row + c0))[1];
            t[0] += __half2float(yl0.x);
            t[1] += __half2float(yl0.y);
            t[2] += __half2float(yl1.x);
            t[3] += __half2float(yl1.y);
        }
    }
    float sum = 0.0f, sq = 0.0f;
#pragma unroll
    for (int i = 0; i < 4; i++) {
        if (MODE == 1)
            t[i] = 0.5f * t[i] * (1.0f + erff(t[i] * 0.7071067811865476f));
        sum += t[i];
        sq += t[i] * t[i];
    }
    sum = warpSum(sum);
    sq = warpSum(sq);
    if (lane == 0) { s1[wid] = sum; s2[wid] = sq; }
    __syncthreads();
    float ts = 0.0f, tq = 0.0f;
#pragma unroll
    for (int w = 0; w < 4; w++) { ts += s1[w]; tq += s2[w]; }
    const float mean = ts * (1.0f / 512.0f);
    const float var = tq * (1.0f / 512.0f) - mean * mean;
    const float inv = rsqrtf(var + 1e-5f);

    const float4 gv = *(const float4*)(g + c0);
    const float4 bv = *(const float4*)(b + c0);
    float o[4];
    o[0] = (t[0] - mean) * inv * gv.x + bv.x;
    o[1] = (t[1] - mean) * inv * gv.y + bv.y;
    o[2] = (t[2] - mean) * inv * gv.z + bv.z;
    o[3] = (t[3] - mean) * inv * gv.w + bv.w;
    __half2 h0, l0, h1, l1;
    split2(o[0], o[1], h0, l0);
    split2(o[2], o[3], h1, l1);
    ((__half2*)(Oh + row + c0))[0] = h0;
    ((__half2*)(Oh + row + c0))[1] = h1;
    ((__half2*)(Ol + row + c0))[0] = l0;
    ((__half2*)(Ol + row + c0))[1] = l1;
}

// ---------------- host ----------------
template <typename T>
static T* symaddr(const void* sym)
{
    void* p = nullptr;
    cudaGetSymbolAddress(&p, sym);
    return (T*)p;
}

extern "C" void kernel_launch(void* const* d_in, const int* in_sizes, int n_in,
                              void* d_out, int out_size)
{
    const float* x    = (const float*)d_in[0];
    const float* Wq   = (const float*)d_in[1];
    const float* bq   = (const float*)d_in[2];
    const float* Wk   = (const float*)d_in[3];
    const float* bk   = (const float*)d_in[4];
    const float* Wv   = (const float*)d_in[5];
    const float* bv   = (const float*)d_in[6];
    const float* ln0g = (const float*)d_in[7];
    const float* ln0b = (const float*)d_in[8];
    const float* W1   = (const float*)d_in[9];
    const float* b1   = (const float*)d_in[10];
    const float* ln1g = (const float*)d_in[11];
    const float* ln1b = (const float*)d_in[12];
    const float* W2   = (const float*)d_in[13];
    const float* b2   = (const float*)d_in[14];
    const float* ln2g = (const float*)d_in[15];
    const float* ln2b = (const float*)d_in[16];
    const float* W3   = (const float*)d_in[17];
    const float* b3   = (const float*)d_in[18];
    float* out = (float*)d_out;

    __half* xh  = symaddr<__half>(g_xh);
    __half* yh  = symaddr<__half>(g_yh);
    __half* vth = symaddr<__half>(g_vth);
    __half* ath = symaddr<__half>(g_ath);
    __half* onh = symaddr<__half>(g_onh);  __half* onl = symaddr<__half>(g_onl);
    __half* th  = symaddr<__half>(g_th);   __half* tl  = symaddr<__half>(g_tl);
    __half* hh  = symaddr<__half>(g_hh);   __half* hl  = symaddr<__half>(g_hl);
    __half* h2h = symaddr<__half>(g_h2h);  __half* h2l = symaddr<__half>(g_h2l);
    __half* sh_ = symaddr<__half>(g_sh);
    __half* wth = symaddr<__half>(g_wth);
    __half* wqh = symaddr<__half>(g_wqh);
    __half* wkh = symaddr<__half>(g_wkh);
    float* u  = symaddr<float>(g_u);
    float* c  = symaddr<float>(g_c);

    cudaFuncSetAttribute(mma_gemm_h,    cudaFuncAttributeMaxDynamicSharedMemorySize, SMEM_H);
    cudaFuncSetAttribute(mma_gemm<1,2>, cudaFuncAttributeMaxDynamicSharedMemorySize, SMEM_P1);
    cudaFuncSetAttribute(mma_gemm<2,0>, cudaFuncAttributeMaxDynamicSharedMemorySize, SMEM_P2);
    cudaFuncSetAttribute(mma_gemm<2,1>, cudaFuncAttributeMaxDynamicSharedMemorySize, SMEM_P2);

    const long long sSD = 2048LL * 512;
    const long long sSS = 2048LL * 2048;
    const long long WSZ = 512LL * 512;
    const float scale = 0.044194173824159216f;   // 1/sqrt(512)

    dim3 gProj(4, 128, 1);
    dim3 gScores(16, 16, 8);
    dim3 gVt(128, 4, 1);
    dim3 gAtt(4, 16, 8);

    // 1-4: inputs for M path
    tohalf_kernel<<<MTOT / 1024, 256>>>(x, xh, MTOT / 4);
    tohalf_kernel<<<256, 256>>>(Wq, wqh, 65536);
    tohalf_kernel<<<256, 256>>>(Wk, wkh, 65536);
    uvec_kernel<<<64, 256>>>(Wk, bq, u, scale);

    // 5: Mt = scale * Wk @ Wq^T (B-operand for y GEMM), fp32 acc
    mma_gemm<1,2><<<dim3(4, 4, 1), 256, SMEM_P1>>>(wkh, nullptr, wqh,
        nullptr, nullptr, wth, nullptr, 512, 512, 512, 512, scale, 0, 0, 0);

    // 6: y = x @ M  (ncu profiles this launch)
    mma_gemm_h<<<gProj, 256, SMEM_H>>>(xh, wth,
        nullptr, 2, yh, 512, 512, 512, 512, 1.0f, 0, 0, 0);

    // 7: c[i] = x_i . u
    cvec_kernel<<<2048, 256>>>(xh, u, c);

    // 8: scores = y @ x^T (fp16 acc)
    mma_gemm_h<<<gScores, 256, SMEM_H>>>(yh, xh,
        nullptr, 2, sh_, 512, 512, 2048, 512, 1.0f, sSD, sSD, sSS);

    // 9: softmax (+c) in-place
    softmax_kernel<<<16384, 256>>>(sh_, c);

    // 10: merged weight transposes (Wv,W1,W2,W3 -> slots 2..5)
    tsplit4_kernel<<<dim3(16, 16, 4), 256>>>(Wv, W1, W2, W3, wth + 2 * WSZ);

    // 11: v^T = Wv^T @ x^T (row bias bv)
    mma_gemm_h<<<gVt, 256, SMEM_H>>>(wth + 2 * WSZ, xh,
        bv, 1, vth, 512, 512, 16384, 512, 1.0f, 0, 0, 0);

    // 12: att = w @ v (fp32 acc) -> fp16 hi
    mma_gemm<1,2><<<gAtt, 256, SMEM_P1>>>(sh_, nullptr, vth,
        nullptr, nullptr, ath, nullptr, 2048, 16384, 512, 2048, 1.0f,
        sSS, 2048, sSD);

    // 13: out_nxt = LN(x + att)
    rowln_kernel<0, false, false><<<16384, 128>>>(
        x, nullptr, nullptr, ath, nullptr, ln0g, ln0b, onh, onl);

    // 14-15: h1
    mma_gemm<2,1><<<gProj, 256, SMEM_P2>>>(onh, onl, wth + 3 * WSZ,
        b1, nullptr, th, tl, 512, 512, 512, 512, 1.0f, 0, 0, 0);
    rowln_kernel<1, true, true><<<16384, 128>>>(
        nullptr, onh, onl, th, tl, ln1g, ln1b, hh, hl);

    // 16-17: h2
    mma_gemm<2,1><<<gProj, 256, SMEM_P2>>>(hh, hl, wth + 4 * WSZ,
        b2, nullptr, th, tl, 512, 512, 512, 512, 1.0f, 0, 0, 0);
    rowln_kernel<1, true, true><<<16384, 128>>>(
        nullptr, onh, onl, th, tl, ln2g, ln2b, h2h, h2l);

    // 18: out = h2 @ W3 + b3 (fp32)
    mma_gemm<2,0><<<gProj, 256, SMEM_P2>>>(h2h, h2l, wth + 5 * WSZ,
        b3, out, nullptr, nullptr, 512, 512, 512, 512, 1.0f, 0, 0, 0);
}

// round 15
// speedup vs baseline: 1.2428x; 1.1385x over previous
#include <cuda_runtime.h>
#include <cuda_fp16.h>
#include <math.h>
#include <stdint.h>

// ===========================================================================
// AttentionBlock B=8,S=2048,D=512 — mma.sync fp16, precision-tiered GEMMs
// R15: R14 + FFN GEMMs demoted to NPROD=1 (fp32 acc, hi-only A),
//      lo-planes dropped for h1/h2/pre-activations.
// ===========================================================================

#define MTOT (16384 * 512)
__device__ __half g_xh[MTOT];
__device__ __half g_yh[MTOT];                       // y = x @ M
__device__ __half g_vth[MTOT];                      // v^T [512][16384]
__device__ __half g_ath[MTOT];                      // att fp16
__device__ __half g_onh[MTOT], g_onl[MTOT];
__device__ __half g_th[MTOT];                       // FFN pre-activation (hi)
__device__ __half g_hh[MTOT];                       // h1 (hi)
__device__ __half g_h2h[MTOT];                      // h2 (hi)
__device__ __half g_sh[8LL * 2048 * 2048];
__device__ __half g_wth[6 * 512 * 512];             // slot0=Mt, 2..5 = Wv,W1,W2,W3 ^T
__device__ __half g_wqh[512 * 512], g_wkh[512 * 512];
__device__ float g_u[512];
__device__ float g_c[16384];

// ---------------- helpers ----------------
__device__ __forceinline__ uint32_t smem_u32(const void* p) {
    uint32_t a;
    asm("{ .reg .u64 t; cvta.to.shared.u64 t, %1; cvt.u32.u64 %0, t; }"
        : "=r"(a) : "l"(p));
    return a;
}
__device__ __forceinline__ void cpa16(uint32_t dst, const void* src) {
    asm volatile("cp.async.cg.shared.global [%0], [%1], 16;"
                 :: "r"(dst), "l"(src) : "memory");
}
#define CP_COMMIT() asm volatile("cp.async.commit_group;" ::: "memory")
#define CP_WAIT0()  asm volatile("cp.async.wait_group 0;"  ::: "memory")
#define CP_WAIT1()  asm volatile("cp.async.wait_group 1;"  ::: "memory")
#define CP_WAIT2()  asm volatile("cp.async.wait_group 2;"  ::: "memory")

#define MMA_F16(c, a0, a1, a2, a3, b0, b1)                                    \
    asm volatile("mma.sync.aligned.m16n8k16.row.col.f32.f16.f16.f32 "         \
        "{%0,%1,%2,%3}, {%4,%5,%6,%7}, {%8,%9}, {%0,%1,%2,%3};"               \
        : "+f"((c)[0]), "+f"((c)[1]), "+f"((c)[2]), "+f"((c)[3])              \
        : "r"(a0), "r"(a1), "r"(a2), "r"(a3), "r"(b0), "r"(b1))

#define MMA_H16(c, a0, a1, a2, a3, b0, b1)                                    \
    asm volatile("mma.sync.aligned.m16n8k16.row.col.f16.f16.f16.f16 "         \
        "{%0,%1}, {%2,%3,%4,%5}, {%6,%7}, {%0,%1};"                           \
        : "+r"((c)[0]), "+r"((c)[1])                                          \
        : "r"(a0), "r"(a1), "r"(a2), "r"(a3), "r"(b0), "r"(b1))

__device__ __forceinline__ void ldsm_x4(uint32_t& r0, uint32_t& r1,
                                        uint32_t& r2, uint32_t& r3, uint32_t a) {
    asm volatile("ldmatrix.sync.aligned.m8n8.x4.shared.b16 {%0,%1,%2,%3}, [%4];"
                 : "=r"(r0), "=r"(r1), "=r"(r2), "=r"(r3) : "r"(a));
}

__device__ __forceinline__ void split2(float a, float b, __half2& h, __half2& l) {
    h = __floats2half2_rn(a, b);
    l = __floats2half2_rn(a - __half2float(h.x), b - __half2float(h.y));
}

#define RSTRIDE 80
#define PLANE_B 10240
#define SMEM_H  (3 * 2 * PLANE_B)
#define SMEM_P1 (4 * 2 * PLANE_B)

// ===========================================================================
// fp16-accumulator GEMM. biasMode: 0=col, 1=row, 2=none.
// ===========================================================================
__global__ __launch_bounds__(256, 3) void mma_gemm_h(
    const __half* __restrict__ Ah, const __half* __restrict__ Bh,
    const float* __restrict__ bias, int biasMode,
    __half* __restrict__ Ch,
    int ldA, int ldB, int ldC, int K, float alpha,
    long long sA, long long sB, long long sC)
{
    constexpr int NSTG = 3;
    constexpr uint32_t STAGE = 2 * PLANE_B;
    constexpr uint32_t BOFF  = PLANE_B;

    extern __shared__ __align__(16) uint32_t sm[];
    const uint32_t sbase = smem_u32(sm);

    const int bz = blockIdx.z;
    Ah += (long long)bz * sA;
    Bh += (long long)bz * sB;

    const int m0 = blockIdx.y * 128;
    const int n0 = blockIdx.x * 128;
    const int tid  = threadIdx.x;
    const int wid  = tid >> 5, lane = tid & 31;
    const int wm   = wid >> 2, wn = wid & 3;
    const int g    = lane >> 2, t = lane & 3;

    const int lrow = tid >> 1;
    const int lseg = (tid & 1) * 2;
    const char* gAh = (const char*)(Ah + (long long)(m0 + lrow) * ldA) + lseg * 16;
    const char* gBh = (const char*)(Bh + (long long)(n0 + lrow) * ldB) + lseg * 16;
    const uint32_t dst0 = sbase + lrow * RSTRIDE + lseg * 16;

    const uint32_t a_off = (uint32_t)(wm * 64 + (lane & 15)) * RSTRIDE
                         + (uint32_t)(lane >> 4) * 16u;
    const uint32_t b_off = (uint32_t)(wn * 32 + (lane & 7) + ((lane >> 4) & 1) * 8) * RSTRIDE
                         + (uint32_t)((lane >> 3) & 1) * 16u;

    uint32_t acc[4][4][2];
#pragma unroll
    for (int i = 0; i < 4; i++)
#pragma unroll
        for (int j = 0; j < 4; j++) { acc[i][j][0] = 0u; acc[i][j][1] = 0u; }

    const int NCH = K >> 5;

    auto PREF = [&](int chv) {
        const uint32_t so = (uint32_t)(chv % NSTG) * STAGE;
        const long long go = (long long)chv * 64;
        cpa16(dst0 + so,             gAh + go);
        cpa16(dst0 + so + 16,        gAh + go + 16);
        cpa16(dst0 + so + BOFF,      gBh + go);
        cpa16(dst0 + so + BOFF + 16, gBh + go + 16);
    };

    {
        const int npre = (NCH < 2) ? NCH : 2;
        for (int i = 0; i < npre; i++) { PREF(i); CP_COMMIT(); }
    }
    for (int ch = 0; ch < NCH; ch++) {
        const int rem = NCH - 1 - ch;
        if (rem <= 0) CP_WAIT0(); else CP_WAIT1();
        __syncthreads();
        if (ch + 2 < NCH) { PREF(ch + 2); CP_COMMIT(); }

        const uint32_t sb = sbase + (uint32_t)(ch % NSTG) * STAGE;
        const uint32_t aA = sb + a_off;
        const uint32_t aB = sb + BOFF + b_off;
#pragma unroll
        for (int ks = 0; ks < 2; ks++) {
            const uint32_t ko = ks * 32;
            uint32_t bh[4][2];
            ldsm_x4(bh[0][0], bh[0][1], bh[1][0], bh[1][1], aB + ko);
            ldsm_x4(bh[2][0], bh[2][1], bh[3][0], bh[3][1], aB + 16 * RSTRIDE + ko);
#pragma unroll
            for (int mi = 0; mi < 4; mi++) {
                uint32_t ah[4];
                ldsm_x4(ah[0], ah[1], ah[2], ah[3], aA + mi * 16 * RSTRIDE + ko);
#pragma unroll
                for (int ni = 0; ni < 4; ni++)
                    MMA_H16(acc[mi][ni], ah[0], ah[1], ah[2], ah[3],
                            bh[ni][0], bh[ni][1]);
            }
        }
    }

    __half* ChB = Ch + (long long)bz * sC;
    const __half2 alph = __half2half2(__float2half(alpha));
#pragma unroll
    for (int mi = 0; mi < 4; mi++) {
#pragma unroll
        for (int ni = 0; ni < 4; ni++) {
            const int r0 = m0 + wm * 64 + mi * 16 + g;
            const int c  = n0 + wn * 32 + ni * 8 + t * 2;
            __half2 v0 = __hmul2(*(__half2*)&acc[mi][ni][0], alph);
            __half2 v1 = __hmul2(*(__half2*)&acc[mi][ni][1], alph);
            if (biasMode == 0) {
                const __half2 bb = __floats2half2_rn(bias[c], bias[c + 1]);
                v0 = __hadd2(v0, bb);
                v1 = __hadd2(v1, bb);
            } else if (biasMode == 1) {
                v0 = __hadd2(v0, __float2half2_rn(bias[r0]));
                v1 = __hadd2(v1, __float2half2_rn(bias[r0 + 8]));
            }
            ((__half2*)ChB)[((long long)r0 * ldC + c) >> 1]       = v0;
            ((__half2*)ChB)[((long long)(r0 + 8) * ldC + c) >> 1] = v1;
        }
    }
}

// ===========================================================================
// fp32-accumulator GEMM, single-product (A hi only). OUTM: 0=fp32; 2=fp16 hi.
// bias is col-mode when non-null.
// ===========================================================================
template <int OUTM>
__global__ __launch_bounds__(256, 2) void mma_gemm(
    const __half* __restrict__ Ah, const __half* __restrict__ Bh,
    const float* __restrict__ bias,
    float* __restrict__ Cf, __half* __restrict__ Ch,
    int ldA, int ldB, int ldC, int K, float alpha,
    long long sA, long long sB, long long sC)
{
    constexpr int NSTG = 4;
    constexpr uint32_t STAGE = 2 * PLANE_B;
    constexpr uint32_t BOFF  = PLANE_B;

    extern __shared__ __align__(16) uint32_t sm[];
    const uint32_t sbase = smem_u32(sm);

    const int bz = blockIdx.z;
    Ah += (long long)bz * sA;
    Bh += (long long)bz * sB;

    const int m0 = blockIdx.y * 128;
    const int n0 = blockIdx.x * 128;
    const int tid  = threadIdx.x;
    const int wid  = tid >> 5, lane = tid & 31;
    const int wm   = wid >> 2, wn = wid & 3;
    const int g    = lane >> 2, t = lane & 3;

    const int lrow = tid >> 1;
    const int lseg = (tid & 1) * 2;
    const char* gAh = (const char*)(Ah + (long long)(m0 + lrow) * ldA) + lseg * 16;
    const char* gBh = (const char*)(Bh + (long long)(n0 + lrow) * ldB) + lseg * 16;
    const uint32_t dst0 = sbase + lrow * RSTRIDE + lseg * 16;

    const uint32_t a_off = (uint32_t)(wm * 64 + (lane & 15)) * RSTRIDE
                         + (uint32_t)(lane >> 4) * 16u;
    const uint32_t b_off = (uint32_t)(wn * 32 + (lane & 7) + ((lane >> 4) & 1) * 8) * RSTRIDE
                         + (uint32_t)((lane >> 3) & 1) * 16u;

    float acc[4][4][4];
#pragma unroll
    for (int i = 0; i < 4; i++)
#pragma unroll
        for (int j = 0; j < 4; j++)
#pragma unroll
            for (int e = 0; e < 4; e++) acc[i][j][e] = 0.0f;

    const int NCH = K >> 5;

    auto PREF = [&](int chv) {
        const uint32_t so = (uint32_t)(chv % NSTG) * STAGE;
        const long long go = (long long)chv * 64;
        cpa16(dst0 + so,      gAh + go);
        cpa16(dst0 + so + 16, gAh + go + 16);
        cpa16(dst0 + so + BOFF,      gBh + go);
        cpa16(dst0 + so + BOFF + 16, gBh + go + 16);
    };

    {
        const int npre = (NCH < NSTG - 1) ? NCH : (NSTG - 1);
        for (int i = 0; i < npre; i++) { PREF(i); CP_COMMIT(); }
    }
    for (int ch = 0; ch < NCH; ch++) {
        int w = NSTG - 2;
        const int rem = NCH - 1 - ch;
        if (rem < w) w = rem;
        if (w <= 0)      CP_WAIT0();
        else if (w == 1) CP_WAIT1();
        else             CP_WAIT2();
        __syncthreads();
        if (ch + NSTG - 1 < NCH) { PREF(ch + NSTG - 1); CP_COMMIT(); }

        const uint32_t sb = sbase + (uint32_t)(ch % NSTG) * STAGE;
        const uint32_t aA = sb + a_off;
        const uint32_t aB = sb + BOFF + b_off;
#pragma unroll
        for (int ks = 0; ks < 2; ks++) {
            const uint32_t ko = ks * 32;
            uint32_t bh[4][2];
            ldsm_x4(bh[0][0], bh[0][1], bh[1][0], bh[1][1], aB + ko);
            ldsm_x4(bh[2][0], bh[2][1], bh[3][0], bh[3][1], aB + 16 * RSTRIDE + ko);
#pragma unroll
            for (int mi = 0; mi < 4; mi++) {
                uint32_t ah[4];
                ldsm_x4(ah[0], ah[1], ah[2], ah[3], aA + mi * 16 * RSTRIDE + ko);
#pragma unroll
                for (int ni = 0; ni < 4; ni++)
                    MMA_F16(acc[mi][ni], ah[0], ah[1], ah[2], ah[3], bh[ni][0], bh[ni][1]);
            }
        }
    }

    float*  CfB = Cf + (long long)bz * sC;
    __half* ChB = Ch + (long long)bz * sC;

#pragma unroll
    for (int mi = 0; mi < 4; mi++) {
#pragma unroll
        for (int ni = 0; ni < 4; ni++) {
            const int r0 = m0 + wm * 64 + mi * 16 + g;
            const int c  = n0 + wn * 32 + ni * 8 + t * 2;
            float v0 = acc[mi][ni][0] * alpha, v1 = acc[mi][ni][1] * alpha;
            float v2 = acc[mi][ni][2] * alpha, v3 = acc[mi][ni][3] * alpha;
            if (bias) {
                const float b0 = bias[c], b1 = bias[c + 1];
                v0 += b0; v1 += b1; v2 += b0; v3 += b1;
            }
            if (OUTM == 0) {
                *(float2*)&CfB[(long long)r0 * ldC + c]       = make_float2(v0, v1);
                *(float2*)&CfB[(long long)(r0 + 8) * ldC + c] = make_float2(v2, v3);
            } else {
                ((__half2*)ChB)[((long long)r0 * ldC + c) >> 1]       = __floats2half2_rn(v0, v1);
                ((__half2*)ChB)[((long long)(r0 + 8) * ldC + c) >> 1] = __floats2half2_rn(v2, v3);
            }
        }
    }
}

// ---------------- fp32 -> fp16 ----------------
__global__ __launch_bounds__(256) void tohalf_kernel(
    const float* __restrict__ in, __half* __restrict__ oh, int n4)
{
    const int i = blockIdx.x * 256 + threadIdx.x;
    if (i >= n4) return;
    float4 v = ((const float4*)in)[i];
    ((__half2*)oh)[i * 2]     = __floats2half2_rn(v.x, v.y);
    ((__half2*)oh)[i * 2 + 1] = __floats2half2_rn(v.z, v.w);
}

// -------- warp reductions --------
__device__ __forceinline__ float warpSum(float v) {
#pragma unroll
    for (int o = 16; o > 0; o >>= 1) v += __shfl_xor_sync(0xffffffffu, v, o);
    return v;
}
__device__ __forceinline__ float warpMax(float v) {
#pragma unroll
    for (int o = 16; o > 0; o >>= 1) v = fmaxf(v, __shfl_xor_sync(0xffffffffu, v, o));
    return v;
}

// ---------------- u = scale * (Wk @ bq): one warp per row ----------------
__global__ __launch_bounds__(256) void uvec_kernel(
    const float* __restrict__ Wk, const float* __restrict__ bq,
    float* __restrict__ u, float scale)
{
    const int row = blockIdx.x * 8 + (threadIdx.x >> 5);
    const int lane = threadIdx.x & 31;
    const float* wr = Wk + (long long)row * 512;
    float s = 0.0f;
#pragma unroll 4
    for (int j = lane; j < 512; j += 32) s += wr[j] * bq[j];
    s = warpSum(s);
    if (lane == 0) u[row] = s * scale;
}

// ---------------- c[i] = x_i . u  (one warp per row) ----------------
__global__ __launch_bounds__(256) void cvec_kernel(
    const __half* __restrict__ xh, const float* __restrict__ u,
    float* __restrict__ c)
{
    const int warp = (blockIdx.x * 256 + threadIdx.x) >> 5;
    const int lane = threadIdx.x & 31;
    const __half2* xr = (const __half2*)(xh + (long long)warp * 512);
    float s = 0.0f;
#pragma unroll 4
    for (int j = lane; j < 256; j += 32) {
        const __half2 hv = xr[j];
        s += __half2float(hv.x) * u[2 * j] + __half2float(hv.y) * u[2 * j + 1];
    }
    s = warpSum(s);
    if (lane == 0) c[warp] = s;
}

// ------ merged transpose: 4 weights fp32 [512][512] -> fp16 W^T slots ------
__global__ __launch_bounds__(256) void tsplit4_kernel(
    const float* __restrict__ W0, const float* __restrict__ W1,
    const float* __restrict__ W2, const float* __restrict__ W3,
    __half* __restrict__ outBase)
{
    __shared__ float tile[32][33];
    const int z = blockIdx.z;
    const float* in = (z == 0) ? W0 : (z == 1) ? W1 : (z == 2) ? W2 : W3;
    __half* oh = outBase + (long long)z * 512 * 512;
    const int c0 = blockIdx.x * 32, r0 = blockIdx.y * 32;
    const int tx = threadIdx.x & 31, ty = threadIdx.x >> 5;

#pragma unroll
    for (int i = 0; i < 4; i++)
        tile[ty + i * 8][tx] = in[(long long)(r0 + ty + i * 8) * 512 + c0 + tx];
    __syncthreads();
#pragma unroll
    for (int i = 0; i < 4; i++) {
        const float v = tile[tx][ty + i * 8];
        oh[(long long)(c0 + ty + i * 8) * 512 + r0 + tx] = __float2half_rn(v);
    }
}

// -------- softmax, in-place, logits += c[col] --------
__global__ __launch_bounds__(256) void softmax_kernel(
    __half* __restrict__ H, const float* __restrict__ c)
{
    const long long base = (long long)blockIdx.x * 2048;
    const float* cb = c + (long long)(blockIdx.x >> 11) * 2048;
    __half2* rh = (__half2*)(H + base);
    const int tid = threadIdx.x;
    const int lane = tid & 31, wid = tid >> 5;
    __shared__ float sh[8];

    float v[8];
#pragma unroll
    for (int j = 0; j < 4; j++) {
        const __half2 hv = rh[tid * 4 + j];
        v[2*j]   = __half2float(hv.x) + cb[tid * 8 + 2 * j];
        v[2*j+1] = __half2float(hv.y) + cb[tid * 8 + 2 * j + 1];
    }

    float m = v[0];
#pragma unroll
    for (int i = 1; i < 8; i++) m = fmaxf(m, v[i]);
    m = warpMax(m);
    if (lane == 0) sh[wid] = m;
    __syncthreads();
    m = sh[0];
#pragma unroll
    for (int w = 1; w < 8; w++) m = fmaxf(m, sh[w]);

    float e[8];
    float s = 0.0f;
#pragma unroll
    for (int i = 0; i < 8; i++) { e[i] = __expf(v[i] - m); s += e[i]; }
    s = warpSum(s);
    __syncthreads();
    if (lane == 0) sh[wid] = s;
    __syncthreads();
    float tot = 0.0f;
#pragma unroll
    for (int w = 0; w < 8; w++) tot += sh[w];
    const float inv = 1.0f / tot;

#pragma unroll
    for (int j = 0; j < 4; j++)
        rh[tid * 4 + j] = __floats2half2_rn(e[2*j] * inv, e[2*j+1] * inv);
}

// ---------------- fused add(+gelu)+LN, vectorized fp16 I/O ------------
// X: XPAIR ? Xh+Xl : fp32 Xf.  Y: hi (+lo if YPAIR).  Output: hi (+lo if WLO).
template <int MODE, bool XPAIR, bool YPAIR, bool WLO>
__global__ __launch_bounds__(128) void rowln_kernel(
    const float* __restrict__ Xf,
    const __half* __restrict__ Xh, const __half* __restrict__ Xl,
    const __half* __restrict__ Yh, const __half* __restrict__ Yl,
    const float* __restrict__ g, const float* __restrict__ b,
    __half* __restrict__ Oh, __half* __restrict__ Ol)
{
    const long long row = (long long)blockIdx.x * 512;
    const int tid = threadIdx.x;
    const int lane = tid & 31, wid = tid >> 5;
    const int c0 = tid * 4;
    __shared__ float s1[4], s2[4];

    float t[4];
    {
        float xv[4];
        if (XPAIR) {
            const __half2 xh0 = ((const __half2*)(Xh + row + c0))[0];
            const __half2 xh1 = ((const __half2*)(Xh + row + c0))[1];
            const __half2 xl0 = ((const __half2*)(Xl + row + c0))[0];
            const __half2 xl1 = ((const __half2*)(Xl + row + c0))[1];
            xv[0] = __half2float(xh0.x) + __half2float(xl0.x);
            xv[1] = __half2float(xh0.y) + __half2float(xl0.y);
            xv[2] = __half2float(xh1.x) + __half2float(xl1.x);
            xv[3] = __half2float(xh1.y) + __half2float(xl1.y);
        } else {
            const float4 xf = *(const float4*)(Xf + row + c0);
            xv[0] = xf.x; xv[1] = xf.y; xv[2] = xf.z; xv[3] = xf.w;
        }
        const __half2 yh0 = ((const __half2*)(Yh + row + c0))[0];
        const __half2 yh1 = ((const __half2*)(Yh + row + c0))[1];
        t[0] = xv[0] + __half2float(yh0.x);
        t[1] = xv[1] + __half2float(yh0.y);
        t[2] = xv[2] + __half2float(yh1.x);
        t[3] = xv[3] + __half2float(yh1.y);
        if (YPAIR) {
            const __half2 yl0 = ((const __half2*)(Yl + row + c0))[0];
            const __half2 yl1 = ((const __half2*)(Yl + row + c0))[1];
            t[0] += __half2float(yl0.x);
            t[1] += __half2float(yl0.y);
            t[2] += __half2float(yl1.x);
            t[3] += __half2float(yl1.y);
        }
    }
    float sum = 0.0f, sq = 0.0f;
#pragma unroll
    for (int i = 0; i < 4; i++) {
        if (MODE == 1)
            t[i] = 0.5f * t[i] * (1.0f + erff(t[i] * 0.7071067811865476f));
        sum += t[i];
        sq += t[i] * t[i];
    }
    sum = warpSum(sum);
    sq = warpSum(sq);
    if (lane == 0) { s1[wid] = sum; s2[wid] = sq; }
    __syncthreads();
    float ts = 0.0f, tq = 0.0f;
#pragma unroll
    for (int w = 0; w < 4; w++) { ts += s1[w]; tq += s2[w]; }
    const float mean = ts * (1.0f / 512.0f);
    const float var = tq * (1.0f / 512.0f) - mean * mean;
    const float inv = rsqrtf(var + 1e-5f);

    const float4 gv = *(const float4*)(g + c0);
    const float4 bv = *(const float4*)(b + c0);
    float o[4];
    o[0] = (t[0] - mean) * inv * gv.x + bv.x;
    o[1] = (t[1] - mean) * inv * gv.y + bv.y;
    o[2] = (t[2] - mean) * inv * gv.z + bv.z;
    o[3] = (t[3] - mean) * inv * gv.w + bv.w;
    if (WLO) {
        __half2 h0, l0, h1, l1;
        split2(o[0], o[1], h0, l0);
        split2(o[2], o[3], h1, l1);
        ((__half2*)(Oh + row + c0))[0] = h0;
        ((__half2*)(Oh + row + c0))[1] = h1;
        ((__half2*)(Ol + row + c0))[0] = l0;
        ((__half2*)(Ol + row + c0))[1] = l1;
    } else {
        ((__half2*)(Oh + row + c0))[0] = __floats2half2_rn(o[0], o[1]);
        ((__half2*)(Oh + row + c0))[1] = __floats2half2_rn(o[2], o[3]);
    }
}

// ---------------- host ----------------
template <typename T>
static T* symaddr(const void* sym)
{
    void* p = nullptr;
    cudaGetSymbolAddress(&p, sym);
    return (T*)p;
}

extern "C" void kernel_launch(void* const* d_in, const int* in_sizes, int n_in,
                              void* d_out, int out_size)
{
    const float* x    = (const float*)d_in[0];
    const float* Wq   = (const float*)d_in[1];
    const float* bq   = (const float*)d_in[2];
    const float* Wk   = (const float*)d_in[3];
    const float* bk   = (const float*)d_in[4];
    const float* Wv   = (const float*)d_in[5];
    const float* bv   = (const float*)d_in[6];
    const float* ln0g = (const float*)d_in[7];
    const float* ln0b = (const float*)d_in[8];
    const float* W1   = (const float*)d_in[9];
    const float* b1   = (const float*)d_in[10];
    const float* ln1g = (const float*)d_in[11];
    const float* ln1b = (const float*)d_in[12];
    const float* W2   = (const float*)d_in[13];
    const float* b2   = (const float*)d_in[14];
    const float* ln2g = (const float*)d_in[15];
    const float* ln2b = (const float*)d_in[16];
    const float* W3   = (const float*)d_in[17];
    const float* b3   = (const float*)d_in[18];
    float* out = (float*)d_out;

    __half* xh  = symaddr<__half>(g_xh);
    __half* yh  = symaddr<__half>(g_yh);
    __half* vth = symaddr<__half>(g_vth);
    __half* ath = symaddr<__half>(g_ath);
    __half* onh = symaddr<__half>(g_onh);  __half* onl = symaddr<__half>(g_onl);
    __half* th  = symaddr<__half>(g_th);
    __half* hh  = symaddr<__half>(g_hh);
    __half* h2h = symaddr<__half>(g_h2h);
    __half* sh_ = symaddr<__half>(g_sh);
    __half* wth = symaddr<__half>(g_wth);
    __half* wqh = symaddr<__half>(g_wqh);
    __half* wkh = symaddr<__half>(g_wkh);
    float* u  = symaddr<float>(g_u);
    float* c  = symaddr<float>(g_c);

    cudaFuncSetAttribute(mma_gemm_h,  cudaFuncAttributeMaxDynamicSharedMemorySize, SMEM_H);
    cudaFuncSetAttribute(mma_gemm<0>, cudaFuncAttributeMaxDynamicSharedMemorySize, SMEM_P1);
    cudaFuncSetAttribute(mma_gemm<2>, cudaFuncAttributeMaxDynamicSharedMemorySize, SMEM_P1);

    const long long sSD = 2048LL * 512;
    const long long sSS = 2048LL * 2048;
    const long long WSZ = 512LL * 512;
    const float scale = 0.044194173824159216f;   // 1/sqrt(512)

    dim3 gProj(4, 128, 1);
    dim3 gScores(16, 16, 8);
    dim3 gVt(128, 4, 1);
    dim3 gAtt(4, 16, 8);

    // 1-4: inputs for M path
    tohalf_kernel<<<MTOT / 1024, 256>>>(x, xh, MTOT / 4);
    tohalf_kernel<<<256, 256>>>(Wq, wqh, 65536);
    tohalf_kernel<<<256, 256>>>(Wk, wkh, 65536);
    uvec_kernel<<<64, 256>>>(Wk, bq, u, scale);

    // 5: Mt = scale * Wk @ Wq^T (B-operand for y GEMM), fp32 acc
    mma_gemm<2><<<dim3(4, 4, 1), 256, SMEM_P1>>>(wkh, wqh,
        nullptr, nullptr, wth, 512, 512, 512, 512, scale, 0, 0, 0);

    // 6: y = x @ M  (ncu profiles this launch)
    mma_gemm_h<<<gProj, 256, SMEM_H>>>(xh, wth,
        nullptr, 2, yh, 512, 512, 512, 512, 1.0f, 0, 0, 0);

    // 7: c[i] = x_i . u
    cvec_kernel<<<2048, 256>>>(xh, u, c);

    // 8: scores = y @ x^T (fp16 acc)
    mma_gemm_h<<<gScores, 256, SMEM_H>>>(yh, xh,
        nullptr, 2, sh_, 512, 512, 2048, 512, 1.0f, sSD, sSD, sSS);

    // 9: softmax (+c) in-place
    softmax_kernel<<<16384, 256>>>(sh_, c);

    // 10: merged weight transposes (Wv,W1,W2,W3 -> slots 2..5)
    tsplit4_kernel<<<dim3(16, 16, 4), 256>>>(Wv, W1, W2, W3, wth + 2 * WSZ);

    // 11: v^T = Wv^T @ x^T (row bias bv)
    mma_gemm_h<<<gVt, 256, SMEM_H>>>(wth + 2 * WSZ, xh,
        bv, 1, vth, 512, 512, 16384, 512, 1.0f, 0, 0, 0);

    // 12: att = w @ v (fp32 acc) -> fp16 hi
    mma_gemm<2><<<gAtt, 256, SMEM_P1>>>(sh_, vth,
        nullptr, nullptr, ath, 2048, 16384, 512, 2048, 1.0f,
        sSS, 2048, sSD);

    // 13: out_nxt = LN(x + att) -> pair
    rowln_kernel<0, false, false, true><<<16384, 128>>>(
        x, nullptr, nullptr, ath, nullptr, ln0g, ln0b, onh, onl);

    // 14-15: h1 = LN(gelu(on + on@W1 + b1))  [fp32 acc, A hi only]
    mma_gemm<2><<<gProj, 256, SMEM_P1>>>(onh, wth + 3 * WSZ,
        b1, nullptr, th, 512, 512, 512, 512, 1.0f, 0, 0, 0);
    rowln_kernel<1, true, false, false><<<16384, 128>>>(
        nullptr, onh, onl, th, nullptr, ln1g, ln1b, hh, nullptr);

    // 16-17: h2 = LN(gelu(on + h1@W2 + b2))
    mma_gemm<2><<<gProj, 256, SMEM_P1>>>(hh, wth + 4 * WSZ,
        b2, nullptr, th, 512, 512, 512, 512, 1.0f, 0, 0, 0);
    rowln_kernel<1, true, false, false><<<16384, 128>>>(
        nullptr, onh, onl, th, nullptr, ln2g, ln2b, h2h, nullptr);

    // 18: out = h2 @ W3 + b3 (fp32)
    mma_gemm<0><<<gProj, 256, SMEM_P1>>>(h2h, wth + 5 * WSZ,
        b3, out, nullptr, 512, 512, 512, 512, 1.0f, 0, 0, 0);
}

// round 16
// speedup vs baseline: 1.3033x; 1.0487x over previous
#include <cuda_runtime.h>
#include <cuda_fp16.h>
#include <math.h>
#include <stdint.h>

// ===========================================================================
// AttentionBlock B=8,S=2048,D=512 — mma.sync fp16, precision-tiered GEMMs
// R16: R15 + two-stream DAG overlap (uvec/cvec/tsplit4/v^T concurrent with
//      y/scores/softmax chain) via capture-legal event fork/join.
// ===========================================================================

#define MTOT (16384 * 512)
__device__ __half g_xh[MTOT];
__device__ __half g_yh[MTOT];                       // y = x @ M
__device__ __half g_vth[MTOT];                      // v^T [512][16384]
__device__ __half g_ath[MTOT];                      // att fp16
__device__ __half g_onh[MTOT], g_onl[MTOT];
__device__ __half g_th[MTOT];                       // FFN pre-activation (hi)
__device__ __half g_hh[MTOT];                       // h1 (hi)
__device__ __half g_h2h[MTOT];                      // h2 (hi)
__device__ __half g_sh[8LL * 2048 * 2048];
__device__ __half g_wth[6 * 512 * 512];             // slot0=Mt, 2..5 = Wv,W1,W2,W3 ^T
__device__ __half g_wqh[512 * 512], g_wkh[512 * 512];
__device__ float g_u[512];
__device__ float g_c[16384];

// ---------------- helpers ----------------
__device__ __forceinline__ uint32_t smem_u32(const void* p) {
    uint32_t a;
    asm("{ .reg .u64 t; cvta.to.shared.u64 t, %1; cvt.u32.u64 %0, t; }"
        : "=r"(a) : "l"(p));
    return a;
}
__device__ __forceinline__ void cpa16(uint32_t dst, const void* src) {
    asm volatile("cp.async.cg.shared.global [%0], [%1], 16;"
                 :: "r"(dst), "l"(src) : "memory");
}
#define CP_COMMIT() asm volatile("cp.async.commit_group;" ::: "memory")
#define CP_WAIT0()  asm volatile("cp.async.wait_group 0;"  ::: "memory")
#define CP_WAIT1()  asm volatile("cp.async.wait_group 1;"  ::: "memory")
#define CP_WAIT2()  asm volatile("cp.async.wait_group 2;"  ::: "memory")

#define MMA_F16(c, a0, a1, a2, a3, b0, b1)                                    \
    asm volatile("mma.sync.aligned.m16n8k16.row.col.f32.f16.f16.f32 "         \
        "{%0,%1,%2,%3}, {%4,%5,%6,%7}, {%8,%9}, {%0,%1,%2,%3};"               \
        : "+f"((c)[0]), "+f"((c)[1]), "+f"((c)[2]), "+f"((c)[3])              \
        : "r"(a0), "r"(a1), "r"(a2), "r"(a3), "r"(b0), "r"(b1))

#define MMA_H16(c, a0, a1, a2, a3, b0, b1)                                    \
    asm volatile("mma.sync.aligned.m16n8k16.row.col.f16.f16.f16.f16 "         \
        "{%0,%1}, {%2,%3,%4,%5}, {%6,%7}, {%0,%1};"                           \
        : "+r"((c)[0]), "+r"((c)[1])                                          \
        : "r"(a0), "r"(a1), "r"(a2), "r"(a3), "r"(b0), "r"(b1))

__device__ __forceinline__ void ldsm_x4(uint32_t& r0, uint32_t& r1,
                                        uint32_t& r2, uint32_t& r3, uint32_t a) {
    asm volatile("ldmatrix.sync.aligned.m8n8.x4.shared.b16 {%0,%1,%2,%3}, [%4];"
                 : "=r"(r0), "=r"(r1), "=r"(r2), "=r"(r3) : "r"(a));
}

__device__ __forceinline__ void split2(float a, float b, __half2& h, __half2& l) {
    h = __floats2half2_rn(a, b);
    l = __floats2half2_rn(a - __half2float(h.x), b - __half2float(h.y));
}

#define RSTRIDE 80
#define PLANE_B 10240
#define SMEM_H  (3 * 2 * PLANE_B)
#define SMEM_P1 (4 * 2 * PLANE_B)

// ===========================================================================
// fp16-accumulator GEMM. biasMode: 0=col, 1=row, 2=none.
// ===========================================================================
__global__ __launch_bounds__(256, 3) void mma_gemm_h(
    const __half* __restrict__ Ah, const __half* __restrict__ Bh,
    const float* __restrict__ bias, int biasMode,
    __half* __restrict__ Ch,
    int ldA, int ldB, int ldC, int K, float alpha,
    long long sA, long long sB, long long sC)
{
    constexpr int NSTG = 3;
    constexpr uint32_t STAGE = 2 * PLANE_B;
    constexpr uint32_t BOFF  = PLANE_B;

    extern __shared__ __align__(16) uint32_t sm[];
    const uint32_t sbase = smem_u32(sm);

    const int bz = blockIdx.z;
    Ah += (long long)bz * sA;
    Bh += (long long)bz * sB;

    const int m0 = blockIdx.y * 128;
    const int n0 = blockIdx.x * 128;
    const int tid  = threadIdx.x;
    const int wid  = tid >> 5, lane = tid & 31;
    const int wm   = wid >> 2, wn = wid & 3;
    const int g    = lane >> 2, t = lane & 3;

    const int lrow = tid >> 1;
    const int lseg = (tid & 1) * 2;
    const char* gAh = (const char*)(Ah + (long long)(m0 + lrow) * ldA) + lseg * 16;
    const char* gBh = (const char*)(Bh + (long long)(n0 + lrow) * ldB) + lseg * 16;
    const uint32_t dst0 = sbase + lrow * RSTRIDE + lseg * 16;

    const uint32_t a_off = (uint32_t)(wm * 64 + (lane & 15)) * RSTRIDE
                         + (uint32_t)(lane >> 4) * 16u;
    const uint32_t b_off = (uint32_t)(wn * 32 + (lane & 7) + ((lane >> 4) & 1) * 8) * RSTRIDE
                         + (uint32_t)((lane >> 3) & 1) * 16u;

    uint32_t acc[4][4][2];
#pragma unroll
    for (int i = 0; i < 4; i++)
#pragma unroll
        for (int j = 0; j < 4; j++) { acc[i][j][0] = 0u; acc[i][j][1] = 0u; }

    const int NCH = K >> 5;

    auto PREF = [&](int chv) {
        const uint32_t so = (uint32_t)(chv % NSTG) * STAGE;
        const long long go = (long long)chv * 64;
        cpa16(dst0 + so,             gAh + go);
        cpa16(dst0 + so + 16,        gAh + go + 16);
        cpa16(dst0 + so + BOFF,      gBh + go);
        cpa16(dst0 + so + BOFF + 16, gBh + go + 16);
    };

    {
        const int npre = (NCH < 2) ? NCH : 2;
        for (int i = 0; i < npre; i++) { PREF(i); CP_COMMIT(); }
    }
    for (int ch = 0; ch < NCH; ch++) {
        const int rem = NCH - 1 - ch;
        if (rem <= 0) CP_WAIT0(); else CP_WAIT1();
        __syncthreads();
        if (ch + 2 < NCH) { PREF(ch + 2); CP_COMMIT(); }

        const uint32_t sb = sbase + (uint32_t)(ch % NSTG) * STAGE;
        const uint32_t aA = sb + a_off;
        const uint32_t aB = sb + BOFF + b_off;
#pragma unroll
        for (int ks = 0; ks < 2; ks++) {
            const uint32_t ko = ks * 32;
            uint32_t bh[4][2];
            ldsm_x4(bh[0][0], bh[0][1], bh[1][0], bh[1][1], aB + ko);
            ldsm_x4(bh[2][0], bh[2][1], bh[3][0], bh[3][1], aB + 16 * RSTRIDE + ko);
#pragma unroll
            for (int mi = 0; mi < 4; mi++) {
                uint32_t ah[4];
                ldsm_x4(ah[0], ah[1], ah[2], ah[3], aA + mi * 16 * RSTRIDE + ko);
#pragma unroll
                for (int ni = 0; ni < 4; ni++)
                    MMA_H16(acc[mi][ni], ah[0], ah[1], ah[2], ah[3],
                            bh[ni][0], bh[ni][1]);
            }
        }
    }

    __half* ChB = Ch + (long long)bz * sC;
    const __half2 alph = __half2half2(__float2half(alpha));
#pragma unroll
    for (int mi = 0; mi < 4; mi++) {
#pragma unroll
        for (int ni = 0; ni < 4; ni++) {
            const int r0 = m0 + wm * 64 + mi * 16 + g;
            const int c  = n0 + wn * 32 + ni * 8 + t * 2;
            __half2 v0 = __hmul2(*(__half2*)&acc[mi][ni][0], alph);
            __half2 v1 = __hmul2(*(__half2*)&acc[mi][ni][1], alph);
            if (biasMode == 0) {
                const __half2 bb = __floats2half2_rn(bias[c], bias[c + 1]);
                v0 = __hadd2(v0, bb);
                v1 = __hadd2(v1, bb);
            } else if (biasMode == 1) {
                v0 = __hadd2(v0, __float2half2_rn(bias[r0]));
                v1 = __hadd2(v1, __float2half2_rn(bias[r0 + 8]));
            }
            ((__half2*)ChB)[((long long)r0 * ldC + c) >> 1]       = v0;
            ((__half2*)ChB)[((long long)(r0 + 8) * ldC + c) >> 1] = v1;
        }
    }
}

// ===========================================================================
// fp32-accumulator GEMM, single-product. OUTM: 0=fp32; 2=fp16 hi.
// ===========================================================================
template <int OUTM>
__global__ __launch_bounds__(256, 2) void mma_gemm(
    const __half* __restrict__ Ah, const __half* __restrict__ Bh,
    const float* __restrict__ bias,
    float* __restrict__ Cf, __half* __restrict__ Ch,
    int ldA, int ldB, int ldC, int K, float alpha,
    long long sA, long long sB, long long sC)
{
    constexpr int NSTG = 4;
    constexpr uint32_t STAGE = 2 * PLANE_B;
    constexpr uint32_t BOFF  = PLANE_B;

    extern __shared__ __align__(16) uint32_t sm[];
    const uint32_t sbase = smem_u32(sm);

    const int bz = blockIdx.z;
    Ah += (long long)bz * sA;
    Bh += (long long)bz * sB;

    const int m0 = blockIdx.y * 128;
    const int n0 = blockIdx.x * 128;
    const int tid  = threadIdx.x;
    const int wid  = tid >> 5, lane = tid & 31;
    const int wm   = wid >> 2, wn = wid & 3;
    const int g    = lane >> 2, t = lane & 3;

    const int lrow = tid >> 1;
    const int lseg = (tid & 1) * 2;
    const char* gAh = (const char*)(Ah + (long long)(m0 + lrow) * ldA) + lseg * 16;
    const char* gBh = (const char*)(Bh + (long long)(n0 + lrow) * ldB) + lseg * 16;
    const uint32_t dst0 = sbase + lrow * RSTRIDE + lseg * 16;

    const uint32_t a_off = (uint32_t)(wm * 64 + (lane & 15)) * RSTRIDE
                         + (uint32_t)(lane >> 4) * 16u;
    const uint32_t b_off = (uint32_t)(wn * 32 + (lane & 7) + ((lane >> 4) & 1) * 8) * RSTRIDE
                         + (uint32_t)((lane >> 3) & 1) * 16u;

    float acc[4][4][4];
#pragma unroll
    for (int i = 0; i < 4; i++)
#pragma unroll
        for (int j = 0; j < 4; j++)
#pragma unroll
            for (int e = 0; e < 4; e++) acc[i][j][e] = 0.0f;

    const int NCH = K >> 5;

    auto PREF = [&](int chv) {
        const uint32_t so = (uint32_t)(chv % NSTG) * STAGE;
        const long long go = (long long)chv * 64;
        cpa16(dst0 + so,      gAh + go);
        cpa16(dst0 + so + 16, gAh + go + 16);
        cpa16(dst0 + so + BOFF,      gBh + go);
        cpa16(dst0 + so + BOFF + 16, gBh + go + 16);
    };

    {
        const int npre = (NCH < NSTG - 1) ? NCH : (NSTG - 1);
        for (int i = 0; i < npre; i++) { PREF(i); CP_COMMIT(); }
    }
    for (int ch = 0; ch < NCH; ch++) {
        int w = NSTG - 2;
        const int rem = NCH - 1 - ch;
        if (rem < w) w = rem;
        if (w <= 0)      CP_WAIT0();
        else if (w == 1) CP_WAIT1();
        else             CP_WAIT2();
        __syncthreads();
        if (ch + NSTG - 1 < NCH) { PREF(ch + NSTG - 1); CP_COMMIT(); }

        const uint32_t sb = sbase + (uint32_t)(ch % NSTG) * STAGE;
        const uint32_t aA = sb + a_off;
        const uint32_t aB = sb + BOFF + b_off;
#pragma unroll
        for (int ks = 0; ks < 2; ks++) {
            const uint32_t ko = ks * 32;
            uint32_t bh[4][2];
            ldsm_x4(bh[0][0], bh[0][1], bh[1][0], bh[1][1], aB + ko);
            ldsm_x4(bh[2][0], bh[2][1], bh[3][0], bh[3][1], aB + 16 * RSTRIDE + ko);
#pragma unroll
            for (int mi = 0; mi < 4; mi++) {
                uint32_t ah[4];
                ldsm_x4(ah[0], ah[1], ah[2], ah[3], aA + mi * 16 * RSTRIDE + ko);
#pragma unroll
                for (int ni = 0; ni < 4; ni++)
                    MMA_F16(acc[mi][ni], ah[0], ah[1], ah[2], ah[3], bh[ni][0], bh[ni][1]);
            }
        }
    }

    float*  CfB = Cf + (long long)bz * sC;
    __half* ChB = Ch + (long long)bz * sC;

#pragma unroll
    for (int mi = 0; mi < 4; mi++) {
#pragma unroll
        for (int ni = 0; ni < 4; ni++) {
            const int r0 = m0 + wm * 64 + mi * 16 + g;
            const int c  = n0 + wn * 32 + ni * 8 + t * 2;
            float v0 = acc[mi][ni][0] * alpha, v1 = acc[mi][ni][1] * alpha;
            float v2 = acc[mi][ni][2] * alpha, v3 = acc[mi][ni][3] * alpha;
            if (bias) {
                const float b0 = bias[c], b1 = bias[c + 1];
                v0 += b0; v1 += b1; v2 += b0; v3 += b1;
            }
            if (OUTM == 0) {
                *(float2*)&CfB[(long long)r0 * ldC + c]       = make_float2(v0, v1);
                *(float2*)&CfB[(long long)(r0 + 8) * ldC + c] = make_float2(v2, v3);
            } else {
                ((__half2*)ChB)[((long long)r0 * ldC + c) >> 1]       = __floats2half2_rn(v0, v1);
                ((__half2*)ChB)[((long long)(r0 + 8) * ldC + c) >> 1] = __floats2half2_rn(v2, v3);
            }
        }
    }
}

// ---------------- fp32 -> fp16 ----------------
__global__ __launch_bounds__(256) void tohalf_kernel(
    const float* __restrict__ in, __half* __restrict__ oh, int n4)
{
    const int i = blockIdx.x * 256 + threadIdx.x;
    if (i >= n4) return;
    float4 v = ((const float4*)in)[i];
    ((__half2*)oh)[i * 2]     = __floats2half2_rn(v.x, v.y);
    ((__half2*)oh)[i * 2 + 1] = __floats2half2_rn(v.z, v.w);
}

// -------- warp reductions --------
__device__ __forceinline__ float warpSum(float v) {
#pragma unroll
    for (int o = 16; o > 0; o >>= 1) v += __shfl_xor_sync(0xffffffffu, v, o);
    return v;
}
__device__ __forceinline__ float warpMax(float v) {
#pragma unroll
    for (int o = 16; o > 0; o >>= 1) v = fmaxf(v, __shfl_xor_sync(0xffffffffu, v, o));
    return v;
}

// ---------------- u = scale * (Wk @ bq): one warp per row ----------------
__global__ __launch_bounds__(256) void uvec_kernel(
    const float* __restrict__ Wk, const float* __restrict__ bq,
    float* __restrict__ u, float scale)
{
    const int row = blockIdx.x * 8 + (threadIdx.x >> 5);
    const int lane = threadIdx.x & 31;
    const float* wr = Wk + (long long)row * 512;
    float s = 0.0f;
#pragma unroll 4
    for (int j = lane; j < 512; j += 32) s += wr[j] * bq[j];
    s = warpSum(s);
    if (lane == 0) u[row] = s * scale;
}

// ---------------- c[i] = x_i . u  (one warp per row) ----------------
__global__ __launch_bounds__(256) void cvec_kernel(
    const __half* __restrict__ xh, const float* __restrict__ u,
    float* __restrict__ c)
{
    const int warp = (blockIdx.x * 256 + threadIdx.x) >> 5;
    const int lane = threadIdx.x & 31;
    const __half2* xr = (const __half2*)(xh + (long long)warp * 512);
    float s = 0.0f;
#pragma unroll 4
    for (int j = lane; j < 256; j += 32) {
        const __half2 hv = xr[j];
        s += __half2float(hv.x) * u[2 * j] + __half2float(hv.y) * u[2 * j + 1];
    }
    s = warpSum(s);
    if (lane == 0) c[warp] = s;
}

// ------ merged transpose: 4 weights fp32 [512][512] -> fp16 W^T slots ------
__global__ __launch_bounds__(256) void tsplit4_kernel(
    const float* __restrict__ W0, const float* __restrict__ W1,
    const float* __restrict__ W2, const float* __restrict__ W3,
    __half* __restrict__ outBase)
{
    __shared__ float tile[32][33];
    const int z = blockIdx.z;
    const float* in = (z == 0) ? W0 : (z == 1) ? W1 : (z == 2) ? W2 : W3;
    __half* oh = outBase + (long long)z * 512 * 512;
    const int c0 = blockIdx.x * 32, r0 = blockIdx.y * 32;
    const int tx = threadIdx.x & 31, ty = threadIdx.x >> 5;

#pragma unroll
    for (int i = 0; i < 4; i++)
        tile[ty + i * 8][tx] = in[(long long)(r0 + ty + i * 8) * 512 + c0 + tx];
    __syncthreads();
#pragma unroll
    for (int i = 0; i < 4; i++) {
        const float v = tile[tx][ty + i * 8];
        oh[(long long)(c0 + ty + i * 8) * 512 + r0 + tx] = __float2half_rn(v);
    }
}

// -------- softmax, in-place, logits += c[col] --------
__global__ __launch_bounds__(256) void softmax_kernel(
    __half* __restrict__ H, const float* __restrict__ c)
{
    const long long base = (long long)blockIdx.x * 2048;
    const float* cb = c + (long long)(blockIdx.x >> 11) * 2048;
    __half2* rh = (__half2*)(H + base);
    const int tid = threadIdx.x;
    const int lane = tid & 31, wid = tid >> 5;
    __shared__ float sh[8];

    float v[8];
#pragma unroll
    for (int j = 0; j < 4; j++) {
        const __half2 hv = rh[tid * 4 + j];
        v[2*j]   = __half2float(hv.x) + cb[tid * 8 + 2 * j];
        v[2*j+1] = __half2float(hv.y) + cb[tid * 8 + 2 * j + 1];
    }

    float m = v[0];
#pragma unroll
    for (int i = 1; i < 8; i++) m = fmaxf(m, v[i]);
    m = warpMax(m);
    if (lane == 0) sh[wid] = m;
    __syncthreads();
    m = sh[0];
#pragma unroll
    for (int w = 1; w < 8; w++) m = fmaxf(m, sh[w]);

    float e[8];
    float s = 0.0f;
#pragma unroll
    for (int i = 0; i < 8; i++) { e[i] = __expf(v[i] - m); s += e[i]; }
    s = warpSum(s);
    __syncthreads();
    if (lane == 0) sh[wid] = s;
    __syncthreads();
    float tot = 0.0f;
#pragma unroll
    for (int w = 0; w < 8; w++) tot += sh[w];
    const float inv = 1.0f / tot;

#pragma unroll
    for (int j = 0; j < 4; j++)
        rh[tid * 4 + j] = __floats2half2_rn(e[2*j] * inv, e[2*j+1] * inv);
}

// ---------------- fused add(+gelu)+LN ----------------
template <int MODE, bool XPAIR, bool YPAIR, bool WLO>
__global__ __launch_bounds__(128) void rowln_kernel(
    const float* __restrict__ Xf,
    const __half* __restrict__ Xh, const __half* __restrict__ Xl,
    const __half* __restrict__ Yh, const __half* __restrict__ Yl,
    const float* __restrict__ g, const float* __restrict__ b,
    __half* __restrict__ Oh, __half* __restrict__ Ol)
{
    const long long row = (long long)blockIdx.x * 512;
    const int tid = threadIdx.x;
    const int lane = tid & 31, wid = tid >> 5;
    const int c0 = tid * 4;
    __shared__ float s1[4], s2[4];

    float t[4];
    {
        float xv[4];
        if (XPAIR) {
            const __half2 xh0 = ((const __half2*)(Xh + row + c0))[0];
            const __half2 xh1 = ((const __half2*)(Xh + row + c0))[1];
            const __half2 xl0 = ((const __half2*)(Xl + row + c0))[0];
            const __half2 xl1 = ((const __half2*)(Xl + row + c0))[1];
            xv[0] = __half2float(xh0.x) + __half2float(xl0.x);
            xv[1] = __half2float(xh0.y) + __half2float(xl0.y);
            xv[2] = __half2float(xh1.x) + __half2float(xl1.x);
            xv[3] = __half2float(xh1.y) + __half2float(xl1.y);
        } else {
            const float4 xf = *(const float4*)(Xf + row + c0);
            xv[0] = xf.x; xv[1] = xf.y; xv[2] = xf.z; xv[3] = xf.w;
        }
        const __half2 yh0 = ((const __half2*)(Yh + row + c0))[0];
        const __half2 yh1 = ((const __half2*)(Yh + row + c0))[1];
        t[0] = xv[0] + __half2float(yh0.x);
        t[1] = xv[1] + __half2float(yh0.y);
        t[2] = xv[2] + __half2float(yh1.x);
        t[3] = xv[3] + __half2float(yh1.y);
        if (YPAIR) {
            const __half2 yl0 = ((const __half2*)(Yl + row + c0))[0];
            const __half2 yl1 = ((const __half2*)(Yl + row + c0))[1];
            t[0] += __half2float(yl0.x);
            t[1] += __half2float(yl0.y);
            t[2] += __half2float(yl1.x);
            t[3] += __half2float(yl1.y);
        }
    }
    float sum = 0.0f, sq = 0.0f;
#pragma unroll
    for (int i = 0; i < 4; i++) {
        if (MODE == 1)
            t[i] = 0.5f * t[i] * (1.0f + erff(t[i] * 0.7071067811865476f));
        sum += t[i];
        sq += t[i] * t[i];
    }
    sum = warpSum(sum);
    sq = warpSum(sq);
    if (lane == 0) { s1[wid] = sum; s2[wid] = sq; }
    __syncthreads();
    float ts = 0.0f, tq = 0.0f;
#pragma unroll
    for (int w = 0; w < 4; w++) { ts += s1[w]; tq += s2[w]; }
    const float mean = ts * (1.0f / 512.0f);
    const float var = tq * (1.0f / 512.0f) - mean * mean;
    const float inv = rsqrtf(var + 1e-5f);

    const float4 gv = *(const float4*)(g + c0);
    const float4 bv = *(const float4*)(b + c0);
    float o[4];
    o[0] = (t[0] - mean) * inv * gv.x + bv.x;
    o[1] = (t[1] - mean) * inv * gv.y + bv.y;
    o[2] = (t[2] - mean) * inv * gv.z + bv.z;
    o[3] = (t[3] - mean) * inv * gv.w + bv.w;
    if (WLO) {
        __half2 h0, l0, h1, l1;
        split2(o[0], o[1], h0, l0);
        split2(o[2], o[3], h1, l1);
        ((__half2*)(Oh + row + c0))[0] = h0;
        ((__half2*)(Oh + row + c0))[1] = h1;
        ((__half2*)(Ol + row + c0))[0] = l0;
        ((__half2*)(Ol + row + c0))[1] = l1;
    } else {
        ((__half2*)(Oh + row + c0))[0] = __floats2half2_rn(o[0], o[1]);
        ((__half2*)(Oh + row + c0))[1] = __floats2half2_rn(o[2], o[3]);
    }
}

// ---------------- host ----------------
template <typename T>
static T* symaddr(const void* sym)
{
    void* p = nullptr;
    cudaGetSymbolAddress(&p, sym);
    return (T*)p;
}

extern "C" void kernel_launch(void* const* d_in, const int* in_sizes, int n_in,
                              void* d_out, int out_size)
{
    const float* x    = (const float*)d_in[0];
    const float* Wq   = (const float*)d_in[1];
    const float* bq   = (const float*)d_in[2];
    const float* Wk   = (const float*)d_in[3];
    const float* bk   = (const float*)d_in[4];
    const float* Wv   = (const float*)d_in[5];
    const float* bv   = (const float*)d_in[6];
    const float* ln0g = (const float*)d_in[7];
    const float* ln0b = (const float*)d_in[8];
    const float* W1   = (const float*)d_in[9];
    const float* b1   = (const float*)d_in[10];
    const float* ln1g = (const float*)d_in[11];
    const float* ln1b = (const float*)d_in[12];
    const float* W2   = (const float*)d_in[13];
    const float* b2   = (const float*)d_in[14];
    const float* ln2g = (const float*)d_in[15];
    const float* ln2b = (const float*)d_in[16];
    const float* W3   = (const float*)d_in[17];
    const float* b3   = (const float*)d_in[18];
    float* out = (float*)d_out;

    __half* xh  = symaddr<__half>(g_xh);
    __half* yh  = symaddr<__half>(g_yh);
    __half* vth = symaddr<__half>(g_vth);
    __half* ath = symaddr<__half>(g_ath);
    __half* onh = symaddr<__half>(g_onh);  __half* onl = symaddr<__half>(g_onl);
    __half* th  = symaddr<__half>(g_th);
    __half* hh  = symaddr<__half>(g_hh);
    __half* h2h = symaddr<__half>(g_h2h);
    __half* sh_ = symaddr<__half>(g_sh);
    __half* wth = symaddr<__half>(g_wth);
    __half* wqh = symaddr<__half>(g_wqh);
    __half* wkh = symaddr<__half>(g_wkh);
    float* u  = symaddr<float>(g_u);
    float* c  = symaddr<float>(g_c);

    cudaFuncSetAttribute(mma_gemm_h,  cudaFuncAttributeMaxDynamicSharedMemorySize, SMEM_H);
    cudaFuncSetAttribute(mma_gemm<0>, cudaFuncAttributeMaxDynamicSharedMemorySize, SMEM_P1);
    cudaFuncSetAttribute(mma_gemm<2>, cudaFuncAttributeMaxDynamicSharedMemorySize, SMEM_P1);

    const long long sSD = 2048LL * 512;
    const long long sSS = 2048LL * 2048;
    const long long WSZ = 512LL * 512;
    const float scale = 0.044194173824159216f;   // 1/sqrt(512)

    dim3 gProj(4, 128, 1);
    dim3 gScores(16, 16, 8);
    dim3 gVt(128, 4, 1);
    dim3 gAtt(4, 16, 8);

    // stream fork (capture-legal: event fork/join; host objects only)
    cudaStream_t sB;
    cudaStreamCreateWithFlags(&sB, cudaStreamNonBlocking);
    cudaEvent_t eX, eC, eVt;
    cudaEventCreateWithFlags(&eX,  cudaEventDisableTiming);
    cudaEventCreateWithFlags(&eC,  cudaEventDisableTiming);
    cudaEventCreateWithFlags(&eVt, cudaEventDisableTiming);

    // main: x -> fp16
    tohalf_kernel<<<MTOT / 1024, 256>>>(x, xh, MTOT / 4);
    cudaEventRecord(eX, 0);

    // stream B: uvec -> cvec -> [eC] -> tsplit4 -> v^T -> [eVt]
    cudaStreamWaitEvent(sB, eX, 0);
    uvec_kernel<<<64, 256, 0, sB>>>(Wk, bq, u, scale);
    cvec_kernel<<<2048, 256, 0, sB>>>(xh, u, c);
    cudaEventRecord(eC, sB);
    tsplit4_kernel<<<dim3(16, 16, 4), 256, 0, sB>>>(Wv, W1, W2, W3, wth + 2 * WSZ);
    mma_gemm_h<<<gVt, 256, SMEM_H, sB>>>(wth + 2 * WSZ, xh,
        bv, 1, vth, 512, 512, 16384, 512, 1.0f, 0, 0, 0);
    cudaEventRecord(eVt, sB);

    // main chain
    tohalf_kernel<<<256, 256>>>(Wq, wqh, 65536);
    tohalf_kernel<<<256, 256>>>(Wk, wkh, 65536);
    mma_gemm<2><<<dim3(4, 4, 1), 256, SMEM_P1>>>(wkh, wqh,
        nullptr, nullptr, wth, 512, 512, 512, 512, scale, 0, 0, 0);
    mma_gemm_h<<<gProj, 256, SMEM_H>>>(xh, wth,
        nullptr, 2, yh, 512, 512, 512, 512, 1.0f, 0, 0, 0);
    mma_gemm_h<<<gScores, 256, SMEM_H>>>(yh, xh,
        nullptr, 2, sh_, 512, 512, 2048, 512, 1.0f, sSD, sSD, sSS);

    cudaStreamWaitEvent(0, eC, 0);
    softmax_kernel<<<16384, 256>>>(sh_, c);

    cudaStreamWaitEvent(0, eVt, 0);
    mma_gemm<2><<<gAtt, 256, SMEM_P1>>>(sh_, vth,
        nullptr, nullptr, ath, 2048, 16384, 512, 2048, 1.0f,
        sSS, 2048, sSD);

    rowln_kernel<0, false, false, true><<<16384, 128>>>(
        x, nullptr, nullptr, ath, nullptr, ln0g, ln0b, onh, onl);

    mma_gemm<2><<<gProj, 256, SMEM_P1>>>(onh, wth + 3 * WSZ,
        b1, nullptr, th, 512, 512, 512, 512, 1.0f, 0, 0, 0);
    rowln_kernel<1, true, false, false><<<16384, 128>>>(
        nullptr, onh, onl, th, nullptr, ln1g, ln1b, hh, nullptr);

    mma_gemm<2><<<gProj, 256, SMEM_P1>>>(hh, wth + 4 * WSZ,
        b2, nullptr, th, 512, 512, 512, 512, 1.0f, 0, 0, 0);
    rowln_kernel<1, true, false, false><<<16384, 128>>>(
        nullptr, onh, onl, th, nullptr, ln2g, ln2b, h2h, nullptr);

    mma_gemm<0><<<gProj, 256, SMEM_P1>>>(h2h, wth + 5 * WSZ,
        b3, out, nullptr, 512, 512, 512, 512, 1.0f, 0, 0, 0);
}